// round 1
// baseline (speedup 1.0000x reference)
#include <cuda_runtime.h>
#include <math.h>

#define NEDGE 65536
#define NATOMS 2048
#define NRADB 24
#define RMLP_O 120   // NRAD*NCOMP
#define NK 69
#define NFEAT 216
#define EMBD 16
#define F_IN 3456
#define H1D 256
#define H2D 128

// ---------------- scratch (device globals; no allocs allowed) ----------------
__device__ float g_rad[(size_t)NEDGE * RMLP_O];   // [E][120], col = r*5 + c
__device__ float g_gij[(size_t)NEDGE * NK];       // [E][69]
__device__ float g_x  [(size_t)NATOMS * F_IN];    // [nat][3456]
__device__ float g_h1 [(size_t)NATOMS * H1D];
__device__ float g_h2 [(size_t)NATOMS * H2D];

// ---------------- angular tables (lx,ly,lz, fnorm, lambda) -------------------
// zeta=1: k 0..3, zeta=2: 4..13, zeta=3: 14..33, zeta=4: 34..68
__constant__ int c_lx[NK] = {
 0,0,0,1,
 0,0,0,1,0,0,0,1,1,2,
 0,0,0,1,0,0,0,1,1,2,0,0,0,0,1,1,1,2,2,3,
 0,0,0,1,0,0,0,1,1,2,0,0,0,0,1,1,1,2,2,3,0,0,0,0,0,1,1,1,1,2,2,2,3,3,4};
__constant__ int c_ly[NK] = {
 0,0,1,0,
 0,0,1,0,0,1,2,0,1,0,
 0,0,1,0,0,1,2,0,1,0,0,1,2,3,0,1,2,0,1,0,
 0,0,1,0,0,1,2,0,1,0,0,1,2,3,0,1,2,0,1,0,0,1,2,3,4,0,1,2,3,0,1,2,0,1,0};
__constant__ int c_lz[NK] = {
 0,1,0,0,
 0,1,0,0,2,1,0,1,0,0,
 0,1,0,0,2,1,0,1,0,0,3,2,1,0,2,1,0,1,0,0,
 0,1,0,0,2,1,0,1,0,0,3,2,1,0,2,1,0,1,0,0,4,3,2,1,0,3,2,1,0,2,1,0,1,0,0};
__constant__ float c_fn[NK] = {
 1,1,1,1,
 1,2,2,2,1,2,1,2,2,1,
 1,3,3,3,3,6,3,6,6,3,1,3,3,1,3,6,3,3,3,1,
 1,4,4,4,6,12,6,12,12,6,4,12,12,4,12,24,12,12,12,4,1,4,6,4,1,4,12,12,4,6,12,6,4,4,1};
__constant__ float c_lam[NK] = {
 1,-1,-1,-1,
 1,-1,-1,-1,1,1,1,1,1,1,
 1,-1,-1,-1,1,1,1,1,1,1,-1,-1,-1,-1,-1,-1,-1,-1,-1,-1,
 1,-1,-1,-1,1,1,1,1,1,1,-1,-1,-1,-1,-1,-1,-1,-1,-1,-1,1,1,1,1,1,1,1,1,1,1,1,1,1,1,1};

__device__ __forceinline__ float silu(float x) {
    return x / (1.0f + expf(-x));
}

// ============================================================================
// Kernel 1: per-edge radial MLP (24 -> 64 -> 120) + angular combos g_ij[69]
// ============================================================================
__global__ __launch_bounds__(128) void edge_kernel(
    const float* __restrict__ rij,
    const float* __restrict__ Wr1, const float* __restrict__ br1,
    const float* __restrict__ Wr2, const float* __restrict__ br2)
{
    __shared__ float sW1[24 * 64];
    __shared__ float sb1[64];
    __shared__ float sW2[64 * 120];
    __shared__ float sb2[120];
    int t = threadIdx.x;
    for (int i = t; i < 24 * 64; i += 128) sW1[i] = Wr1[i];
    for (int i = t; i < 64; i += 128)      sb1[i] = br1[i];
    for (int i = t; i < 64 * 120; i += 128) sW2[i] = Wr2[i];
    for (int i = t; i < 120; i += 128)     sb2[i] = br2[i];
    __syncthreads();

    int e = blockIdx.x * 128 + t;
    float x = rij[e * 3 + 0], y = rij[e * 3 + 1], z = rij[e * 3 + 2];
    float r = sqrtf(x * x + y * y + z * z);
    float inv = 1.0f / r;
    float ux = x * inv, uy = y * inv, uz = z * inv;
    float rc = fminf(r, 6.0f);
    float fc = 0.5f * (cosf(3.14159265358979f * rc * (1.0f / 6.0f)) + 1.0f);

    // gaussian basis, width = 0.25 -> 1/(2w^2) = 8
    float basis[24];
    #pragma unroll
    for (int i = 0; i < 24; i++) {
        float d = r - (6.0f * (float)i / 23.0f);
        basis[i] = expf(-8.0f * d * d) * fc;
    }
    // hidden 64
    float h[64];
    #pragma unroll
    for (int j = 0; j < 64; j++) {
        float s = sb1[j];
        #pragma unroll
        for (int i = 0; i < 24; i++) s = fmaf(basis[i], sW1[i * 64 + j], s);
        h[j] = silu(s);
    }
    // output 120 = [r*5 + c]
    float* out = g_rad + (size_t)e * RMLP_O;
    #pragma unroll 4
    for (int o = 0; o < 120; o++) {
        float s = sb2[o];
        #pragma unroll
        for (int j = 0; j < 64; j++) s = fmaf(h[j], sW2[j * 120 + o], s);
        out[o] = silu(s);
    }
    // angular combos: g_ij[k] = (ux+eps)^lx (uy+eps)^ly (uz+eps)^lz * fnorm
    float bx = ux + 1e-12f, by = uy + 1e-12f, bz = uz + 1e-12f;
    float px[5], py[5], pz[5];
    px[0] = 1.f; py[0] = 1.f; pz[0] = 1.f;
    #pragma unroll
    for (int l = 1; l < 5; l++) {
        px[l] = px[l - 1] * bx; py[l] = py[l - 1] * by; pz[l] = pz[l - 1] * bz;
    }
    float* gg = g_gij + (size_t)e * NK;
    #pragma unroll
    for (int k = 0; k < NK; k++)
        gg[k] = px[c_lx[k]] * py[c_ly[k]] * pz[c_lz[k]] * c_fn[k];
}

// ============================================================================
// Kernel 2: per-atom segment reduction + feature assembly + species embedding
// + outer product x = feat (x) emb  -> g_x[nat][3456]
// One block per atom. Threads 0..68 each own combo k (24 radial accumulators
// in registers); threads 69..92 own one radial channel of the 2-body term.
// ============================================================================
__global__ __launch_bounds__(128) void atom_kernel(
    const int* __restrict__ fa, const int* __restrict__ species,
    const float* __restrict__ Ws1, const float* __restrict__ bs1,
    const float* __restrict__ Ws2, const float* __restrict__ bs2)
{
    __shared__ float sh_gi[NK * 24];
    __shared__ float sh_f0[24];
    __shared__ float sh_feat[NFEAT];
    __shared__ float sh_hv[32];
    __shared__ float sh_emb[EMBD];

    int a = blockIdx.x;
    int t = threadIdx.x;

    // segment bounds via binary search on sorted first_atom_idx
    int lo, hi;
    {
        int l = 0, h = NEDGE;
        while (l < h) { int m = (l + h) >> 1; if (fa[m] < a) l = m + 1; else h = m; }
        lo = l;
        h = NEDGE;
        while (l < h) { int m = (l + h) >> 1; if (fa[m] < a + 1) l = m + 1; else h = m; }
        hi = l;
    }

    if (t < NK) {
        int c = (t < 4) ? 1 : (t < 14) ? 2 : (t < 34) ? 3 : 4;
        float acc[24];
        #pragma unroll
        for (int r = 0; r < 24; r++) acc[r] = 0.f;
        for (int e = lo; e < hi; e++) {
            float g = g_gij[(size_t)e * NK + t];
            const float* rad = g_rad + (size_t)e * RMLP_O + c;
            #pragma unroll
            for (int r = 0; r < 24; r++) acc[r] = fmaf(__ldg(rad + r * 5), g, acc[r]);
        }
        #pragma unroll
        for (int r = 0; r < 24; r++) sh_gi[t * 24 + r] = acc[r];
    } else if (t < NK + 24) {
        int r = t - NK;
        float acc = 0.f;
        for (int e = lo; e < hi; e++) acc += g_rad[(size_t)e * RMLP_O + r * 5];
        sh_f0[r] = acc;
    }
    __syncthreads();

    // features: [0:24]=2-body; then per zeta: lam+ (24), lam- (24)
    for (int f = t; f < NFEAT; f += 128) {
        float v;
        if (f < 24) {
            v = sh_f0[f];
        } else {
            int b   = f - 24;
            int blk = b / 24;       // 0..7
            int r   = b % 24;
            int zi  = blk >> 1;     // zeta index 0..3
            int sgn = blk & 1;      // 0: lambda=+1, 1: lambda=-1
            int ks = (zi == 0) ? 0 : (zi == 1) ? 4 : (zi == 2) ? 14 : 34;
            int ke = (zi == 0) ? 4 : (zi == 1) ? 14 : (zi == 2) ? 34 : 69;
            float s = 0.f;
            for (int k = ks; k < ke; k++) {
                float gv = sh_gi[k * 24 + r];
                float g2 = gv * gv;
                s += sgn ? g2 * c_lam[k] : g2;
            }
            v = s * (1.0f / (float)(1 << zi));   // 2^(1-z), z = zi+1
        }
        sh_feat[f] = v;
    }
    int sp = species[a];
    __syncthreads();

    // species embedding: silu(Ws1[sp] + bs1) @ Ws2 + bs2
    if (t < 32) sh_hv[t] = silu(Ws1[sp * 32 + t] + bs1[t]);
    __syncthreads();
    if (t < EMBD) {
        float acc = bs2[t];
        #pragma unroll
        for (int j = 0; j < 32; j++) acc = fmaf(sh_hv[j], Ws2[j * EMBD + t], acc);
        sh_emb[t] = acc;
    }
    __syncthreads();

    // x[a, f*16 + m] = feat[f] * emb[m]
    float* xo = g_x + (size_t)a * F_IN;
    for (int i = t; i < F_IN; i += 128)
        xo[i] = sh_feat[i >> 4] * sh_emb[i & 15];
}

// ============================================================================
// Tiled fp32 GEMM: C[M,N] = silu(A[M,K] @ B[K,N] + bias[N])
// BM=BN=64, BK=16, 256 threads, 4x4 microtile. M,N,K all divisible.
// ============================================================================
template <int BM, int BN, int BK>
__global__ __launch_bounds__(256) void gemm_bias_silu(
    const float* __restrict__ A, const float* __restrict__ B,
    const float* __restrict__ bias, float* __restrict__ C,
    int M, int N, int K)
{
    __shared__ float As[BK][BM];
    __shared__ float Bs[BK][BN + 4];
    int tid = threadIdx.x;
    int tx = tid % 16, ty = tid / 16;
    int bm = blockIdx.y * BM, bn = blockIdx.x * BN;

    int aRow = tid / 4;            // 0..63
    int aCol = (tid % 4) * 4;      // 0,4,8,12
    int bRow = tid / 16;           // 0..15
    int bCol = (tid % 16) * 4;     // 0..60

    const float* Ab = A + (size_t)bm * K;
    const float* Bb = B + bn;

    float acc[4][4] = {};
    for (int k0 = 0; k0 < K; k0 += BK) {
        float4 av = *(const float4*)(Ab + (size_t)aRow * K + k0 + aCol);
        As[aCol + 0][aRow] = av.x;
        As[aCol + 1][aRow] = av.y;
        As[aCol + 2][aRow] = av.z;
        As[aCol + 3][aRow] = av.w;
        float4 bv = *(const float4*)(Bb + (size_t)(k0 + bRow) * N + bCol);
        *(float4*)&Bs[bRow][bCol] = bv;
        __syncthreads();
        #pragma unroll
        for (int kk = 0; kk < BK; kk++) {
            float ar[4], br[4];
            #pragma unroll
            for (int i = 0; i < 4; i++) ar[i] = As[kk][ty * 4 + i];
            #pragma unroll
            for (int j = 0; j < 4; j++) br[j] = Bs[kk][tx * 4 + j];
            #pragma unroll
            for (int i = 0; i < 4; i++)
                #pragma unroll
                for (int j = 0; j < 4; j++)
                    acc[i][j] = fmaf(ar[i], br[j], acc[i][j]);
        }
        __syncthreads();
    }
    #pragma unroll
    for (int i = 0; i < 4; i++) {
        int m = bm + ty * 4 + i;
        #pragma unroll
        for (int j = 0; j < 4; j++) {
            int n = bn + tx * 4 + j;
            float v = acc[i][j] + bias[n];
            C[(size_t)m * N + n] = silu(v);
        }
    }
}

// ============================================================================
// Final: e[a] = h2[a] . Wa3 + ba3 ; out = sum_a e[a]  (double accumulation)
// ============================================================================
__global__ __launch_bounds__(256) void final_kernel(
    const float* __restrict__ h2, const float* __restrict__ Wa3,
    const float* __restrict__ ba3, float* __restrict__ out)
{
    __shared__ float w[H2D];
    __shared__ double red[256];
    int t = threadIdx.x;
    if (t < H2D) w[t] = Wa3[t];
    __syncthreads();
    float b = ba3[0];
    double s = 0.0;
    for (int a = t; a < NATOMS; a += 256) {
        const float* hp = h2 + (size_t)a * H2D;
        float acc = 0.f;
        #pragma unroll 4
        for (int j = 0; j < H2D; j++) acc = fmaf(hp[j], w[j], acc);
        s += (double)(acc + b);
    }
    red[t] = s;
    __syncthreads();
    for (int off = 128; off > 0; off >>= 1) {
        if (t < off) red[t] += red[t + off];
        __syncthreads();
    }
    if (t == 0) out[0] = (float)red[0];
}

// ============================================================================
extern "C" void kernel_launch(void* const* d_in, const int* in_sizes, int n_in,
                              void* d_out, int out_size)
{
    const float* rij = (const float*)d_in[0];
    const float* Wr1 = (const float*)d_in[1];
    const float* br1 = (const float*)d_in[2];
    const float* Wr2 = (const float*)d_in[3];
    const float* br2 = (const float*)d_in[4];
    const float* Ws1 = (const float*)d_in[5];
    const float* bs1 = (const float*)d_in[6];
    const float* Ws2 = (const float*)d_in[7];
    const float* bs2 = (const float*)d_in[8];
    const float* Wa1 = (const float*)d_in[9];
    const float* ba1 = (const float*)d_in[10];
    const float* Wa2 = (const float*)d_in[11];
    const float* ba2 = (const float*)d_in[12];
    const float* Wa3 = (const float*)d_in[13];
    const float* ba3 = (const float*)d_in[14];
    const int*   fa  = (const int*)d_in[15];
    const int*   sp  = (const int*)d_in[16];
    float* out = (float*)d_out;

    float *px, *ph1, *ph2;
    cudaGetSymbolAddress((void**)&px,  g_x);
    cudaGetSymbolAddress((void**)&ph1, g_h1);
    cudaGetSymbolAddress((void**)&ph2, g_h2);

    edge_kernel<<<NEDGE / 128, 128>>>(rij, Wr1, br1, Wr2, br2);
    atom_kernel<<<NATOMS, 128>>>(fa, sp, Ws1, bs1, Ws2, bs2);
    gemm_bias_silu<64, 64, 16><<<dim3(H1D / 64, NATOMS / 64), 256>>>(
        px, Wa1, ba1, ph1, NATOMS, H1D, F_IN);
    gemm_bias_silu<64, 64, 16><<<dim3(H2D / 64, NATOMS / 64), 256>>>(
        ph1, Wa2, ba2, ph2, NATOMS, H1D /*K=256*/ == H1D ? H2D : H2D, H1D);
    final_kernel<<<1, 256>>>(ph2, Wa3, ba3, out);
}

// round 4
// speedup vs baseline: 1.3763x; 1.3763x over previous
#include <cuda_runtime.h>
#include <math.h>

#define NEDGE 65536
#define NATOMS 2048
#define NRADB 24
#define RMLP_O 120   // NRAD*NCOMP
#define NK 69
#define NFEAT 216
#define EMBD 16
#define NELEM 94
#define H1D 256
#define H2D 128

// ---------------- scratch (device globals; no allocs allowed) ----------------
__device__ float g_rad [(size_t)NEDGE * RMLP_O];      // [E][120], col = r*5 + c
__device__ float g_gij [(size_t)NEDGE * NK];          // [E][69]
__device__ float g_feat[(size_t)NATOMS * NFEAT];      // [nat][216]
__device__ float g_embS[(size_t)NELEM * EMBD];        // [94][16]
__device__ float g_weff[(size_t)NELEM * NFEAT * H1D]; // [94][216][256] 20.8MB
__device__ float g_h1  [(size_t)NATOMS * H1D];
__device__ float g_h2  [(size_t)NATOMS * H2D];
__device__ int   g_start[NELEM + 1];
__device__ int   g_alist[NATOMS];

// ---------------- angular tables (lx,ly,lz, fnorm, lambda) -------------------
// zeta=1: k 0..3, zeta=2: 4..13, zeta=3: 14..33, zeta=4: 34..68
__constant__ int c_lx[NK] = {
 0,0,0,1,
 0,0,0,1,0,0,0,1,1,2,
 0,0,0,1,0,0,0,1,1,2,0,0,0,0,1,1,1,2,2,3,
 0,0,0,1,0,0,0,1,1,2,0,0,0,0,1,1,1,2,2,3,0,0,0,0,0,1,1,1,1,2,2,2,3,3,4};
__constant__ int c_ly[NK] = {
 0,0,1,0,
 0,0,1,0,0,1,2,0,1,0,
 0,0,1,0,0,1,2,0,1,0,0,1,2,3,0,1,2,0,1,0,
 0,0,1,0,0,1,2,0,1,0,0,1,2,3,0,1,2,0,1,0,0,1,2,3,4,0,1,2,3,0,1,2,0,1,0};
__constant__ int c_lz[NK] = {
 0,1,0,0,
 0,1,0,0,2,1,0,1,0,0,
 0,1,0,0,2,1,0,1,0,0,3,2,1,0,2,1,0,1,0,0,
 0,1,0,0,2,1,0,1,0,0,3,2,1,0,2,1,0,1,0,0,4,3,2,1,0,3,2,1,0,2,1,0,1,0,0};
__constant__ float c_fn[NK] = {
 1,1,1,1,
 1,2,2,2,1,2,1,2,2,1,
 1,3,3,3,3,6,3,6,6,3,1,3,3,1,3,6,3,3,3,1,
 1,4,4,4,6,12,6,12,12,6,4,12,12,4,12,24,12,12,12,4,1,4,6,4,1,4,12,12,4,6,12,6,4,4,1};
__constant__ float c_lam[NK] = {
 1,-1,-1,-1,
 1,-1,-1,-1,1,1,1,1,1,1,
 1,-1,-1,-1,1,1,1,1,1,1,-1,-1,-1,-1,-1,-1,-1,-1,-1,-1,
 1,-1,-1,-1,1,1,1,1,1,1,-1,-1,-1,-1,-1,-1,-1,-1,-1,-1,1,1,1,1,1,1,1,1,1,1,1,1,1,1,1};

__device__ __forceinline__ float silu(float x) {
    // x * sigmoid(x) via fast exp + fast reciprocal (err ~1e-6, budget 1e-3)
    return x * __frcp_rn(1.0f + __expf(-x));
}

// ============================================================================
// Kernel 1: per-edge radial MLP (24 -> 64 -> 120) + angular combos g_ij[69]
// ============================================================================
__global__ __launch_bounds__(128) void edge_kernel(
    const float* __restrict__ rij,
    const float* __restrict__ Wr1, const float* __restrict__ br1,
    const float* __restrict__ Wr2, const float* __restrict__ br2)
{
    __shared__ float sW1[24 * 64];
    __shared__ float sb1[64];
    __shared__ float sW2[64 * 120];
    __shared__ float sb2[120];
    int t = threadIdx.x;
    for (int i = t; i < 24 * 64; i += 128) sW1[i] = Wr1[i];
    for (int i = t; i < 64; i += 128)      sb1[i] = br1[i];
    for (int i = t; i < 64 * 120; i += 128) sW2[i] = Wr2[i];
    for (int i = t; i < 120; i += 128)     sb2[i] = br2[i];
    __syncthreads();

    int e = blockIdx.x * 128 + t;
    float x = rij[e * 3 + 0], y = rij[e * 3 + 1], z = rij[e * 3 + 2];
    float r = sqrtf(x * x + y * y + z * z);
    float inv = 1.0f / r;
    float ux = x * inv, uy = y * inv, uz = z * inv;
    float rc = fminf(r, 6.0f);
    float fc = 0.5f * (cosf(3.14159265358979f * rc * (1.0f / 6.0f)) + 1.0f);

    // gaussian basis, width = 0.25 -> 1/(2w^2) = 8
    float basis[24];
    #pragma unroll
    for (int i = 0; i < 24; i++) {
        float d = r - (6.0f * (float)i / 23.0f);
        basis[i] = __expf(-8.0f * d * d) * fc;
    }
    // hidden 64
    float h[64];
    #pragma unroll
    for (int j = 0; j < 64; j++) {
        float s = sb1[j];
        #pragma unroll
        for (int i = 0; i < 24; i++) s = fmaf(basis[i], sW1[i * 64 + j], s);
        h[j] = silu(s);
    }
    // output 120 = [r*5 + c]
    float* out = g_rad + (size_t)e * RMLP_O;
    #pragma unroll 4
    for (int o = 0; o < 120; o++) {
        float s = sb2[o];
        #pragma unroll
        for (int j = 0; j < 64; j++) s = fmaf(h[j], sW2[j * 120 + o], s);
        out[o] = silu(s);
    }
    // angular combos: g_ij[k] = (ux+eps)^lx (uy+eps)^ly (uz+eps)^lz * fnorm
    float bx = ux + 1e-12f, by = uy + 1e-12f, bz = uz + 1e-12f;
    float px[5], py[5], pz[5];
    px[0] = 1.f; py[0] = 1.f; pz[0] = 1.f;
    #pragma unroll
    for (int l = 1; l < 5; l++) {
        px[l] = px[l - 1] * bx; py[l] = py[l - 1] * by; pz[l] = pz[l - 1] * bz;
    }
    float* gg = g_gij + (size_t)e * NK;
    #pragma unroll
    for (int k = 0; k < NK; k++)
        gg[k] = px[c_lx[k]] * py[c_ly[k]] * pz[c_lz[k]] * c_fn[k];
}

// ============================================================================
// Kernel 2: per-atom segment reduction + feature assembly -> g_feat[nat][216]
// Edges staged through smem in chunks of 8 (coalesced gmem reads).
// Threads 0..68 own combo k (24 radial accumulators in registers);
// threads 69..92 own one radial channel of the 2-body term.
// ============================================================================
#define ECHUNK 8
__global__ __launch_bounds__(128) void atom_kernel(const int* __restrict__ fa)
{
    __shared__ float srad[ECHUNK][RMLP_O];   // 3.75KB
    __shared__ float sgij[ECHUNK][NK];       // 2.2KB
    __shared__ float sh_gi[NK * 24];         // 6.6KB
    __shared__ float sh_f0[24];

    int a = blockIdx.x;
    int t = threadIdx.x;

    // segment bounds via binary search on sorted first_atom_idx
    int lo, hi;
    {
        int l = 0, h = NEDGE;
        while (l < h) { int m = (l + h) >> 1; if (fa[m] < a) l = m + 1; else h = m; }
        lo = l;
        h = NEDGE;
        while (l < h) { int m = (l + h) >> 1; if (fa[m] < a + 1) l = m + 1; else h = m; }
        hi = l;
    }

    int c = (t < 4) ? 1 : (t < 14) ? 2 : (t < 34) ? 3 : 4;   // radial component
    float acc[24];
    #pragma unroll
    for (int r = 0; r < 24; r++) acc[r] = 0.f;
    float acc0 = 0.f;

    for (int base = lo; base < hi; base += ECHUNK) {
        int cnt = min(ECHUNK, hi - base);
        for (int idx = t; idx < cnt * RMLP_O; idx += 128) {
            int i = idx / RMLP_O, o = idx % RMLP_O;
            srad[i][o] = g_rad[(size_t)(base + i) * RMLP_O + o];
        }
        for (int idx = t; idx < cnt * NK; idx += 128) {
            int i = idx / NK, k = idx % NK;
            sgij[i][k] = g_gij[(size_t)(base + i) * NK + k];
        }
        __syncthreads();
        if (t < NK) {
            for (int i = 0; i < cnt; i++) {
                float g = sgij[i][t];
                #pragma unroll
                for (int r = 0; r < 24; r++)
                    acc[r] = fmaf(srad[i][r * 5 + c], g, acc[r]);
            }
        } else if (t < NK + 24) {
            int r = t - NK;
            for (int i = 0; i < cnt; i++) acc0 += srad[i][r * 5];
        }
        __syncthreads();
    }

    if (t < NK) {
        #pragma unroll
        for (int r = 0; r < 24; r++) sh_gi[t * 24 + r] = acc[r];
    } else if (t < NK + 24) {
        sh_f0[t - NK] = acc0;
    }
    __syncthreads();

    // features: [0:24]=2-body; then per zeta: lam+ (24), lam- (24)
    float* fo = g_feat + (size_t)a * NFEAT;
    for (int f = t; f < NFEAT; f += 128) {
        float v;
        if (f < 24) {
            v = sh_f0[f];
        } else {
            int b   = f - 24;
            int blk = b / 24;       // 0..7
            int r   = b % 24;
            int zi  = blk >> 1;     // zeta index 0..3
            int sgn = blk & 1;      // 0: lambda=+1, 1: lambda=-1
            int ks = (zi == 0) ? 0 : (zi == 1) ? 4 : (zi == 2) ? 14 : 34;
            int ke = (zi == 0) ? 4 : (zi == 1) ? 14 : (zi == 2) ? 34 : 69;
            float s = 0.f;
            for (int k = ks; k < ke; k++) {
                float gv = sh_gi[k * 24 + r];
                float g2 = gv * gv;
                s += sgn ? g2 * c_lam[k] : g2;
            }
            v = s * (1.0f / (float)(1 << zi));   // 2^(1-z), z = zi+1
        }
        fo[f] = v;
    }
}

// ============================================================================
// Kernel 3: per-species embedding embS[94][16] + counting sort of atoms
// (fused; one block, 256 threads)
// ============================================================================
__global__ __launch_bounds__(256) void embsort_kernel(
    const float* __restrict__ Ws1, const float* __restrict__ bs1,
    const float* __restrict__ Ws2, const float* __restrict__ bs2,
    const int* __restrict__ species)
{
    __shared__ int cnt[NELEM];
    __shared__ int cur[NELEM];
    int t = threadIdx.x;

    if (t < NELEM) {
        int s = t;
        float hv[32];
        #pragma unroll
        for (int j = 0; j < 32; j++) hv[j] = silu(Ws1[s * 32 + j] + bs1[j]);
        #pragma unroll
        for (int m = 0; m < EMBD; m++) {
            float acc = bs2[m];
            #pragma unroll
            for (int j = 0; j < 32; j++) acc = fmaf(hv[j], Ws2[j * EMBD + m], acc);
            g_embS[s * EMBD + m] = acc;
        }
    }

    for (int i = t; i < NELEM; i += 256) cnt[i] = 0;
    __syncthreads();
    for (int a = t; a < NATOMS; a += 256) atomicAdd(&cnt[species[a]], 1);
    __syncthreads();
    if (t == 0) {
        int run = 0;
        for (int s = 0; s < NELEM; s++) {
            g_start[s] = run;
            cur[s] = run;
            run += cnt[s];
        }
        g_start[NELEM] = run;
    }
    __syncthreads();
    for (int a = t; a < NATOMS; a += 256) {
        int s = species[a];
        int pos = atomicAdd(&cur[s], 1);
        g_alist[pos] = a;
    }
}

// ============================================================================
// Kernel 4: W_eff[s][f][n] = sum_m embS[s][m] * Wa1[(f*16+m)*256 + n]
// grid = 216 blocks (one per f), 256 threads (one per n)
// ============================================================================
__global__ __launch_bounds__(256) void weff_kernel(const float* __restrict__ Wa1)
{
    __shared__ float Wsm[EMBD][H1D];    // 16KB
    __shared__ float Esm[NELEM * EMBD]; // 6KB
    int f = blockIdx.x;
    int n = threadIdx.x;
    for (int idx = n; idx < EMBD * H1D; idx += 256) {
        int m = idx / H1D, nn = idx % H1D;
        Wsm[m][nn] = Wa1[(size_t)(f * EMBD + m) * H1D + nn];
    }
    for (int idx = n; idx < NELEM * EMBD; idx += 256) Esm[idx] = g_embS[idx];
    __syncthreads();
    for (int s = 0; s < NELEM; s++) {
        float acc = 0.f;
        #pragma unroll
        for (int m = 0; m < EMBD; m++) acc = fmaf(Esm[s * EMBD + m], Wsm[m][n], acc);
        g_weff[((size_t)s * NFEAT + f) * H1D + n] = acc;
    }
}

// ============================================================================
// Kernel 5: grouped GEMM per species:
//   h1[a, n] = silu( sum_f feat[a,f] * W_eff[s,f,n] + ba1[n] )
// grid = 94 blocks, 256 threads (one per n), 16-atom register blocking
// ============================================================================
#define ACHUNK 16
__global__ __launch_bounds__(256) void gemm1_kernel(const float* __restrict__ ba1)
{
    __shared__ float sf[ACHUNK][NFEAT];   // 13.8KB
    __shared__ int   satom[ACHUNK];
    int s = blockIdx.x;
    int n = threadIdx.x;
    int lo = g_start[s], hi = g_start[s + 1];
    float bias = ba1[n];
    const float* W = g_weff + (size_t)s * NFEAT * H1D + n;

    for (int base = lo; base < hi; base += ACHUNK) {
        int cnt = min(ACHUNK, hi - base);
        if (n < 32) {
            int m = n;
            if (m < ACHUNK) satom[m] = (m < cnt) ? g_alist[base + m] : -1;
        }
        __syncthreads();
        for (int idx = n; idx < ACHUNK * NFEAT; idx += 256) {
            int m = idx / NFEAT, f = idx % NFEAT;
            int a = satom[m];
            sf[m][f] = (a >= 0) ? g_feat[(size_t)a * NFEAT + f] : 0.f;
        }
        __syncthreads();

        float acc[ACHUNK];
        #pragma unroll
        for (int m = 0; m < ACHUNK; m++) acc[m] = 0.f;
        for (int f = 0; f < NFEAT; f += 4) {
            float w0 = W[(size_t)(f + 0) * H1D];
            float w1 = W[(size_t)(f + 1) * H1D];
            float w2 = W[(size_t)(f + 2) * H1D];
            float w3 = W[(size_t)(f + 3) * H1D];
            #pragma unroll
            for (int m = 0; m < ACHUNK; m++) {
                float4 fv = *(const float4*)&sf[m][f];
                acc[m] = fmaf(fv.x, w0, acc[m]);
                acc[m] = fmaf(fv.y, w1, acc[m]);
                acc[m] = fmaf(fv.z, w2, acc[m]);
                acc[m] = fmaf(fv.w, w3, acc[m]);
            }
        }
        #pragma unroll
        for (int m = 0; m < ACHUNK; m++) {
            int a = satom[m];
            if (a >= 0) g_h1[(size_t)a * H1D + n] = silu(acc[m] + bias);
        }
        __syncthreads();
    }
}

// ============================================================================
// Kernel 6: GEMM2, 32x32 tiles: h2 = silu(h1 @ Wa2 + ba2)
// grid (N/32=4, M/32=64) = 256 blocks, 256 threads, 2x2 microtile
// ============================================================================
__global__ __launch_bounds__(256) void gemm2_kernel(
    const float* __restrict__ A, const float* __restrict__ B,
    const float* __restrict__ bias, float* __restrict__ C)
{
    const int N = H2D, K = H1D;
    __shared__ float As[32][33];
    __shared__ float Bs[32][33];
    int tid = threadIdx.x;
    int bm = blockIdx.y * 32, bn = blockIdx.x * 32;
    int lrow = tid / 8;            // 0..31
    int lcol = (tid % 8) * 4;      // 0,4,...,28
    int ty = tid / 16, tx = tid % 16;

    float acc[2][2] = {};
    for (int k0 = 0; k0 < K; k0 += 32) {
        float4 av = *(const float4*)(A + (size_t)(bm + lrow) * K + k0 + lcol);
        As[lcol + 0][lrow] = av.x;
        As[lcol + 1][lrow] = av.y;
        As[lcol + 2][lrow] = av.z;
        As[lcol + 3][lrow] = av.w;
        float4 bv = *(const float4*)(B + (size_t)(k0 + lrow) * N + bn + lcol);
        Bs[lrow][lcol + 0] = bv.x;
        Bs[lrow][lcol + 1] = bv.y;
        Bs[lrow][lcol + 2] = bv.z;
        Bs[lrow][lcol + 3] = bv.w;
        __syncthreads();
        #pragma unroll
        for (int kk = 0; kk < 32; kk++) {
            float a0 = As[kk][ty * 2 + 0];
            float a1 = As[kk][ty * 2 + 1];
            float b0 = Bs[kk][tx * 2 + 0];
            float b1 = Bs[kk][tx * 2 + 1];
            acc[0][0] = fmaf(a0, b0, acc[0][0]);
            acc[0][1] = fmaf(a0, b1, acc[0][1]);
            acc[1][0] = fmaf(a1, b0, acc[1][0]);
            acc[1][1] = fmaf(a1, b1, acc[1][1]);
        }
        __syncthreads();
    }
    #pragma unroll
    for (int i = 0; i < 2; i++) {
        int m = bm + ty * 2 + i;
        #pragma unroll
        for (int j = 0; j < 2; j++) {
            int nn = bn + tx * 2 + j;
            C[(size_t)m * N + nn] = silu(acc[i][j] + bias[nn]);
        }
    }
}

// ============================================================================
// Final: e[a] = h2[a] . Wa3 + ba3 ; out = sum_a e[a]  (double accumulation)
// ============================================================================
__global__ __launch_bounds__(256) void final_kernel(
    const float* __restrict__ h2, const float* __restrict__ Wa3,
    const float* __restrict__ ba3, float* __restrict__ out)
{
    __shared__ float w[H2D];
    __shared__ double red[256];
    int t = threadIdx.x;
    if (t < H2D) w[t] = Wa3[t];
    __syncthreads();
    float b = ba3[0];
    double s = 0.0;
    for (int a = t; a < NATOMS; a += 256) {
        const float* hp = h2 + (size_t)a * H2D;
        float acc = 0.f;
        #pragma unroll 4
        for (int j = 0; j < H2D; j++) acc = fmaf(hp[j], w[j], acc);
        s += (double)(acc + b);
    }
    red[t] = s;
    __syncthreads();
    for (int off = 128; off > 0; off >>= 1) {
        if (t < off) red[t] += red[t + off];
        __syncthreads();
    }
    if (t == 0) out[0] = (float)red[0];
}

// ============================================================================
extern "C" void kernel_launch(void* const* d_in, const int* in_sizes, int n_in,
                              void* d_out, int out_size)
{
    const float* rij = (const float*)d_in[0];
    const float* Wr1 = (const float*)d_in[1];
    const float* br1 = (const float*)d_in[2];
    const float* Wr2 = (const float*)d_in[3];
    const float* br2 = (const float*)d_in[4];
    const float* Ws1 = (const float*)d_in[5];
    const float* bs1 = (const float*)d_in[6];
    const float* Ws2 = (const float*)d_in[7];
    const float* bs2 = (const float*)d_in[8];
    const float* Wa1 = (const float*)d_in[9];
    const float* ba1 = (const float*)d_in[10];
    const float* Wa2 = (const float*)d_in[11];
    const float* ba2 = (const float*)d_in[12];
    const float* Wa3 = (const float*)d_in[13];
    const float* ba3 = (const float*)d_in[14];
    const int*   fa  = (const int*)d_in[15];
    const int*   sp  = (const int*)d_in[16];
    float* out = (float*)d_out;

    float *ph1, *ph2;
    cudaGetSymbolAddress((void**)&ph1, g_h1);
    cudaGetSymbolAddress((void**)&ph2, g_h2);

    edge_kernel<<<NEDGE / 128, 128>>>(rij, Wr1, br1, Wr2, br2);
    atom_kernel<<<NATOMS, 128>>>(fa);
    embsort_kernel<<<1, 256>>>(Ws1, bs1, Ws2, bs2, sp);
    weff_kernel<<<NFEAT, 256>>>(Wa1);
    gemm1_kernel<<<NELEM, 256>>>(ba1);
    gemm2_kernel<<<dim3(H2D / 32, NATOMS / 32), 256>>>(ph1, Wa2, ba2, ph2);
    final_kernel<<<1, 256>>>(ph2, Wa3, ba3, out);
}

// round 5
// speedup vs baseline: 1.9117x; 1.3890x over previous
#include <cuda_runtime.h>
#include <math.h>

#define NEDGE 65536
#define NATOMS 2048
#define NK 69
#define NFEAT 216
#define EMBD 16
#define NELEM 94
#define H1D 256
#define H2D 128
#define EC 32   // edges per chunk in fused kernel

// ---------------- scratch (device globals; no allocs allowed) ----------------
__device__ float g_feat[(size_t)NATOMS * NFEAT];      // [nat][216]
__device__ float g_embS[(size_t)NELEM * EMBD];        // [94][16]
__device__ float g_weff[(size_t)NELEM * NFEAT * H1D]; // [94][216][256] 20.8MB
__device__ float g_h1  [(size_t)NATOMS * H1D];
__device__ float g_h2  [(size_t)NATOMS * H2D];
__device__ int   g_start[NELEM + 1];
__device__ int   g_alist[NATOMS];
__device__ double g_part[8];

// ---------------- angular tables (lx,ly,lz, fnorm, lambda) -------------------
// zeta=1: k 0..3, zeta=2: 4..13, zeta=3: 14..33, zeta=4: 34..68
__constant__ int c_lx[NK] = {
 0,0,0,1,
 0,0,0,1,0,0,0,1,1,2,
 0,0,0,1,0,0,0,1,1,2,0,0,0,0,1,1,1,2,2,3,
 0,0,0,1,0,0,0,1,1,2,0,0,0,0,1,1,1,2,2,3,0,0,0,0,0,1,1,1,1,2,2,2,3,3,4};
__constant__ int c_ly[NK] = {
 0,0,1,0,
 0,0,1,0,0,1,2,0,1,0,
 0,0,1,0,0,1,2,0,1,0,0,1,2,3,0,1,2,0,1,0,
 0,0,1,0,0,1,2,0,1,0,0,1,2,3,0,1,2,0,1,0,0,1,2,3,4,0,1,2,3,0,1,2,0,1,0};
__constant__ int c_lz[NK] = {
 0,1,0,0,
 0,1,0,0,2,1,0,1,0,0,
 0,1,0,0,2,1,0,1,0,0,3,2,1,0,2,1,0,1,0,0,
 0,1,0,0,2,1,0,1,0,0,3,2,1,0,2,1,0,1,0,0,4,3,2,1,0,3,2,1,0,2,1,0,1,0,0};
__constant__ float c_fn[NK] = {
 1,1,1,1,
 1,2,2,2,1,2,1,2,2,1,
 1,3,3,3,3,6,3,6,6,3,1,3,3,1,3,6,3,3,3,1,
 1,4,4,4,6,12,6,12,12,6,4,12,12,4,12,24,12,12,12,4,1,4,6,4,1,4,12,12,4,6,12,6,4,4,1};
__constant__ float c_lam[NK] = {
 1,-1,-1,-1,
 1,-1,-1,-1,1,1,1,1,1,1,
 1,-1,-1,-1,1,1,1,1,1,1,-1,-1,-1,-1,-1,-1,-1,-1,-1,-1,
 1,-1,-1,-1,1,1,1,1,1,1,-1,-1,-1,-1,-1,-1,-1,-1,-1,-1,1,1,1,1,1,1,1,1,1,1,1,1,1,1,1};

__device__ __forceinline__ float silu(float x) {
    // x * sigmoid(x) via fast exp + fast reciprocal (err ~1e-6, budget 1e-3)
    return x * __frcp_rn(1.0f + __expf(-x));
}

// ---------------- fused kernel shared-memory layout (float offsets) ----------
#define OFF_W1T 0        // [64][24] transposed Wr1          1536
#define OFF_B1  1536     // [64]                               64
#define OFF_W2  1600     // [64][120] Wr2 natural            7680
#define OFF_B2  9280     // [120]                             120
#define OFF_BAS 9400     // [EC][25]  basis (padded)          800
#define OFF_H   10200    // [EC][65]  hidden (padded)        2080
#define OFF_RAD 12280    // [EC][121] radial out (padded)    3872
#define OFF_GIJ 16152    // [EC][69]  angular combos         2208
#define OFF_GI  18360    // [69][24]  accumulated gi         1656
#define OFF_F0  20016    // [24]      2-body feature           24
#define SMEM_FLOATS 20040
#define FUSED_SMEM_BYTES (SMEM_FLOATS * 4)

// ============================================================================
// Fused kernel: one block per atom. For each chunk of up to 32 of the atom's
// edges: compute gaussian basis + angular combos (P0), radial MLP layer1 (P1),
// layer2 (P2), then accumulate per-combo gi in registers (P3). After all
// chunks, assemble the 216 features and write g_feat. No per-edge gmem
// intermediates at all.
// Thread roles use (e = t&31, q = t>>5). Weights live in smem, activations in
// registers; weight reads are float4 broadcasts (1 LDS per 4 FMA).
// ============================================================================
__global__ __launch_bounds__(128) void fused_kernel(
    const float* __restrict__ rij,
    const float* __restrict__ Wr1, const float* __restrict__ br1,
    const float* __restrict__ Wr2, const float* __restrict__ br2,
    const int* __restrict__ fa)
{
    extern __shared__ float sm[];
    int a = blockIdx.x;
    int t = threadIdx.x;

    // cooperative weight staging
    for (int idx = t; idx < 1536; idx += 128) {
        int j = idx / 24, i = idx % 24;
        sm[OFF_W1T + idx] = Wr1[i * 64 + j];      // transpose to [j][i]
    }
    for (int idx = t; idx < 64; idx += 128)   sm[OFF_B1 + idx] = br1[idx];
    for (int idx = t; idx < 7680; idx += 128) sm[OFF_W2 + idx] = Wr2[idx];
    for (int idx = t; idx < 120; idx += 128)  sm[OFF_B2 + idx] = br2[idx];

    // segment bounds via binary search on sorted first_atom_idx
    int lo, hi;
    {
        int l = 0, h = NEDGE;
        while (l < h) { int m = (l + h) >> 1; if (fa[m] < a) l = m + 1; else h = m; }
        lo = l;
        h = NEDGE;
        while (l < h) { int m = (l + h) >> 1; if (fa[m] < a + 1) l = m + 1; else h = m; }
        hi = l;
    }

    int c = (t < 4) ? 1 : (t < 14) ? 2 : (t < 34) ? 3 : 4;  // radial comp per combo
    float acc[24];
    #pragma unroll
    for (int r = 0; r < 24; r++) acc[r] = 0.f;
    float acc0 = 0.f;
    int e = t & 31, q = t >> 5;

    for (int base = lo; base < hi; base += EC) {
        int cnt = min(EC, hi - base);
        __syncthreads();   // protect smem reuse (prev P3 reads / weight staging)

        // ---- P0: per-edge geometry: basis + angular combos (threads 0..cnt-1)
        if (t < cnt) {
            int ed = base + t;
            float x = rij[ed * 3 + 0], y = rij[ed * 3 + 1], z = rij[ed * 3 + 2];
            float r = sqrtf(x * x + y * y + z * z);
            float inv = 1.0f / r;
            float ux = x * inv, uy = y * inv, uz = z * inv;
            float rc = fminf(r, 6.0f);
            float fc = 0.5f * (cosf(3.14159265358979f * rc * (1.0f / 6.0f)) + 1.0f);
            #pragma unroll
            for (int i = 0; i < 24; i++) {
                float d = r - (6.0f * (float)i / 23.0f);
                sm[OFF_BAS + t * 25 + i] = __expf(-8.0f * d * d) * fc;
            }
            float bx = ux + 1e-12f, by = uy + 1e-12f, bz = uz + 1e-12f;
            float px[5], py[5], pz[5];
            px[0] = 1.f; py[0] = 1.f; pz[0] = 1.f;
            #pragma unroll
            for (int l = 1; l < 5; l++) {
                px[l] = px[l - 1] * bx; py[l] = py[l - 1] * by; pz[l] = pz[l - 1] * bz;
            }
            #pragma unroll
            for (int k = 0; k < NK; k++)
                sm[OFF_GIJ + t * 69 + k] = px[c_lx[k]] * py[c_ly[k]] * pz[c_lz[k]] * c_fn[k];
        }
        __syncthreads();

        // ---- P1: layer1 h = silu(basis @ W1 + b1); thread (e, q) does 16 j's
        if (e < cnt) {
            float bas[24];
            #pragma unroll
            for (int i = 0; i < 24; i++) bas[i] = sm[OFF_BAS + e * 25 + i];
            #pragma unroll
            for (int jj = 0; jj < 16; jj++) {
                int j = q * 16 + jj;
                float s = sm[OFF_B1 + j];
                #pragma unroll
                for (int i0 = 0; i0 < 24; i0 += 4) {
                    float4 w = *(const float4*)&sm[OFF_W1T + j * 24 + i0];
                    s = fmaf(bas[i0 + 0], w.x, s);
                    s = fmaf(bas[i0 + 1], w.y, s);
                    s = fmaf(bas[i0 + 2], w.z, s);
                    s = fmaf(bas[i0 + 3], w.w, s);
                }
                sm[OFF_H + e * 65 + j] = silu(s);
            }
        }
        __syncthreads();

        // ---- P2: layer2 rad = silu(h @ W2 + b2); thread (e, q) does 4-wide
        //          output groups i in [q*8, min(q*8+8,30))
        if (e < cnt) {
            float hreg[64];
            #pragma unroll
            for (int j = 0; j < 64; j++) hreg[j] = sm[OFF_H + e * 65 + j];
            int ib = q * 8, iend = min(q * 8 + 8, 30);
            for (int i = ib; i < iend; i++) {
                int o0 = i * 4;
                float a0 = sm[OFF_B2 + o0 + 0];
                float a1 = sm[OFF_B2 + o0 + 1];
                float a2 = sm[OFF_B2 + o0 + 2];
                float a3 = sm[OFF_B2 + o0 + 3];
                #pragma unroll
                for (int j = 0; j < 64; j++) {
                    float4 w = *(const float4*)&sm[OFF_W2 + j * 120 + o0];
                    float hv = hreg[j];
                    a0 = fmaf(hv, w.x, a0);
                    a1 = fmaf(hv, w.y, a1);
                    a2 = fmaf(hv, w.z, a2);
                    a3 = fmaf(hv, w.w, a3);
                }
                sm[OFF_RAD + e * 121 + o0 + 0] = silu(a0);
                sm[OFF_RAD + e * 121 + o0 + 1] = silu(a1);
                sm[OFF_RAD + e * 121 + o0 + 2] = silu(a2);
                sm[OFF_RAD + e * 121 + o0 + 3] = silu(a3);
            }
        }
        __syncthreads();

        // ---- P3: accumulate gi[k][r] and 2-body term (register-resident)
        if (t < NK) {
            for (int i = 0; i < cnt; i++) {
                float g = sm[OFF_GIJ + i * 69 + t];
                #pragma unroll
                for (int r = 0; r < 24; r++)
                    acc[r] = fmaf(sm[OFF_RAD + i * 121 + r * 5 + c], g, acc[r]);
            }
        } else if (t < NK + 24) {
            int r = t - NK;
            for (int i = 0; i < cnt; i++) acc0 += sm[OFF_RAD + i * 121 + r * 5];
        }
    }
    __syncthreads();
    if (t < NK) {
        #pragma unroll
        for (int r = 0; r < 24; r++) sm[OFF_GI + t * 24 + r] = acc[r];
    } else if (t < NK + 24) {
        sm[OFF_F0 + t - NK] = acc0;
    }
    __syncthreads();

    // ---- features: [0:24]=2-body; then per zeta: lam+ (24), lam- (24)
    float* fo = g_feat + (size_t)a * NFEAT;
    for (int f = t; f < NFEAT; f += 128) {
        float v;
        if (f < 24) {
            v = sm[OFF_F0 + f];
        } else {
            int b   = f - 24;
            int blk = b / 24;       // 0..7
            int r   = b % 24;
            int zi  = blk >> 1;     // zeta index 0..3
            int sgn = blk & 1;      // 0: lambda=+1, 1: lambda=-1
            int ks = (zi == 0) ? 0 : (zi == 1) ? 4 : (zi == 2) ? 14 : 34;
            int ke = (zi == 0) ? 4 : (zi == 1) ? 14 : (zi == 2) ? 34 : 69;
            float s = 0.f;
            for (int k = ks; k < ke; k++) {
                float gv = sm[OFF_GI + k * 24 + r];
                float g2 = gv * gv;
                s += sgn ? g2 * c_lam[k] : g2;
            }
            v = s * (1.0f / (float)(1 << zi));   // 2^(1-z), z = zi+1
        }
        fo[f] = v;
    }
}

// ============================================================================
// per-species embedding embS[94][16] + counting sort of atoms (one block)
// ============================================================================
__global__ __launch_bounds__(256) void embsort_kernel(
    const float* __restrict__ Ws1, const float* __restrict__ bs1,
    const float* __restrict__ Ws2, const float* __restrict__ bs2,
    const int* __restrict__ species)
{
    __shared__ int cnt[NELEM];
    __shared__ int cur[NELEM];
    int t = threadIdx.x;

    if (t < NELEM) {
        int s = t;
        float hv[32];
        #pragma unroll
        for (int j = 0; j < 32; j++) hv[j] = silu(Ws1[s * 32 + j] + bs1[j]);
        #pragma unroll
        for (int m = 0; m < EMBD; m++) {
            float acc = bs2[m];
            #pragma unroll
            for (int j = 0; j < 32; j++) acc = fmaf(hv[j], Ws2[j * EMBD + m], acc);
            g_embS[s * EMBD + m] = acc;
        }
    }

    for (int i = t; i < NELEM; i += 256) cnt[i] = 0;
    __syncthreads();
    for (int a = t; a < NATOMS; a += 256) atomicAdd(&cnt[species[a]], 1);
    __syncthreads();
    if (t == 0) {
        int run = 0;
        for (int s = 0; s < NELEM; s++) {
            g_start[s] = run;
            cur[s] = run;
            run += cnt[s];
        }
        g_start[NELEM] = run;
    }
    __syncthreads();
    for (int a = t; a < NATOMS; a += 256) {
        int s = species[a];
        int pos = atomicAdd(&cur[s], 1);
        g_alist[pos] = a;
    }
}

// ============================================================================
// W_eff[s][f][n] = sum_m embS[s][m] * Wa1[(f*16+m)*256 + n]
// grid = (216, 4): blockIdx.x = f, blockIdx.y selects 24-species slab
// ============================================================================
__global__ __launch_bounds__(256) void weff_kernel(const float* __restrict__ Wa1)
{
    __shared__ float Wsm[EMBD][H1D];    // 16KB
    __shared__ float Esm[24 * EMBD];    // 1.5KB
    int f = blockIdx.x;
    int s0 = blockIdx.y * 24;
    int s1 = min(s0 + 24, NELEM);
    int nsp = s1 - s0;
    int n = threadIdx.x;
    for (int idx = n; idx < EMBD * H1D; idx += 256) {
        int m = idx / H1D, nn = idx % H1D;
        Wsm[m][nn] = Wa1[(size_t)(f * EMBD + m) * H1D + nn];
    }
    for (int idx = n; idx < nsp * EMBD; idx += 256)
        Esm[idx] = g_embS[s0 * EMBD + idx];
    __syncthreads();
    for (int si = 0; si < nsp; si++) {
        float acc = 0.f;
        #pragma unroll
        for (int m = 0; m < EMBD; m++) acc = fmaf(Esm[si * EMBD + m], Wsm[m][n], acc);
        g_weff[((size_t)(s0 + si) * NFEAT + f) * H1D + n] = acc;
    }
}

// ============================================================================
// grouped GEMM per species: h1[a,n] = silu(sum_f feat[a,f]*W_eff[s,f,n] + ba1)
// grid = 94 blocks, 256 threads (one per n), 16-atom register blocking
// ============================================================================
#define ACHUNK 16
__global__ __launch_bounds__(256) void gemm1_kernel(const float* __restrict__ ba1)
{
    __shared__ float sf[ACHUNK][NFEAT];   // 13.8KB
    __shared__ int   satom[ACHUNK];
    int s = blockIdx.x;
    int n = threadIdx.x;
    int lo = g_start[s], hi = g_start[s + 1];
    float bias = ba1[n];
    const float* W = g_weff + (size_t)s * NFEAT * H1D + n;

    for (int base = lo; base < hi; base += ACHUNK) {
        int cnt = min(ACHUNK, hi - base);
        if (n < ACHUNK) satom[n] = (n < cnt) ? g_alist[base + n] : -1;
        __syncthreads();
        for (int idx = n; idx < ACHUNK * NFEAT; idx += 256) {
            int m = idx / NFEAT, f = idx % NFEAT;
            int a = satom[m];
            sf[m][f] = (a >= 0) ? g_feat[(size_t)a * NFEAT + f] : 0.f;
        }
        __syncthreads();

        float acc[ACHUNK];
        #pragma unroll
        for (int m = 0; m < ACHUNK; m++) acc[m] = 0.f;
        for (int f = 0; f < NFEAT; f += 4) {
            float w0 = W[(size_t)(f + 0) * H1D];
            float w1 = W[(size_t)(f + 1) * H1D];
            float w2 = W[(size_t)(f + 2) * H1D];
            float w3 = W[(size_t)(f + 3) * H1D];
            #pragma unroll
            for (int m = 0; m < ACHUNK; m++) {
                float4 fv = *(const float4*)&sf[m][f];
                acc[m] = fmaf(fv.x, w0, acc[m]);
                acc[m] = fmaf(fv.y, w1, acc[m]);
                acc[m] = fmaf(fv.z, w2, acc[m]);
                acc[m] = fmaf(fv.w, w3, acc[m]);
            }
        }
        #pragma unroll
        for (int m = 0; m < ACHUNK; m++) {
            int a = satom[m];
            if (a >= 0) g_h1[(size_t)a * H1D + n] = silu(acc[m] + bias);
        }
        __syncthreads();
    }
}

// ============================================================================
// GEMM2, 32x32 tiles: h2 = silu(h1 @ Wa2 + ba2); grid (4, 64), 256 threads
// ============================================================================
__global__ __launch_bounds__(256) void gemm2_kernel(
    const float* __restrict__ A, const float* __restrict__ B,
    const float* __restrict__ bias, float* __restrict__ C)
{
    const int N = H2D, K = H1D;
    __shared__ float As[32][33];
    __shared__ float Bs[32][33];
    int tid = threadIdx.x;
    int bm = blockIdx.y * 32, bn = blockIdx.x * 32;
    int lrow = tid / 8;            // 0..31
    int lcol = (tid % 8) * 4;      // 0,4,...,28
    int ty = tid / 16, tx = tid % 16;

    float acc[2][2] = {};
    for (int k0 = 0; k0 < K; k0 += 32) {
        float4 av = *(const float4*)(A + (size_t)(bm + lrow) * K + k0 + lcol);
        As[lcol + 0][lrow] = av.x;
        As[lcol + 1][lrow] = av.y;
        As[lcol + 2][lrow] = av.z;
        As[lcol + 3][lrow] = av.w;
        float4 bv = *(const float4*)(B + (size_t)(k0 + lrow) * N + bn + lcol);
        Bs[lrow][lcol + 0] = bv.x;
        Bs[lrow][lcol + 1] = bv.y;
        Bs[lrow][lcol + 2] = bv.z;
        Bs[lrow][lcol + 3] = bv.w;
        __syncthreads();
        #pragma unroll
        for (int kk = 0; kk < 32; kk++) {
            float a0 = As[kk][ty * 2 + 0];
            float a1 = As[kk][ty * 2 + 1];
            float b0 = Bs[kk][tx * 2 + 0];
            float b1 = Bs[kk][tx * 2 + 1];
            acc[0][0] = fmaf(a0, b0, acc[0][0]);
            acc[0][1] = fmaf(a0, b1, acc[0][1]);
            acc[1][0] = fmaf(a1, b0, acc[1][0]);
            acc[1][1] = fmaf(a1, b1, acc[1][1]);
        }
        __syncthreads();
    }
    #pragma unroll
    for (int i = 0; i < 2; i++) {
        int m = bm + ty * 2 + i;
        #pragma unroll
        for (int j = 0; j < 2; j++) {
            int nn = bn + tx * 2 + j;
            C[(size_t)m * N + nn] = silu(acc[i][j] + bias[nn]);
        }
    }
}

// ============================================================================
// final reduction: 8 blocks x 256 threads (one atom each) -> g_part; then sum
// ============================================================================
__global__ __launch_bounds__(256) void final1_kernel(
    const float* __restrict__ h2, const float* __restrict__ Wa3,
    const float* __restrict__ ba3)
{
    __shared__ float w[H2D];
    __shared__ double red[256];
    int t = threadIdx.x;
    if (t < H2D) w[t] = Wa3[t];
    __syncthreads();
    int a = blockIdx.x * 256 + t;
    const float* hp = h2 + (size_t)a * H2D;
    float acc = 0.f;
    #pragma unroll 4
    for (int j = 0; j < H2D; j++) acc = fmaf(hp[j], w[j], acc);
    red[t] = (double)(acc + ba3[0]);
    __syncthreads();
    for (int off = 128; off > 0; off >>= 1) {
        if (t < off) red[t] += red[t + off];
        __syncthreads();
    }
    if (t == 0) g_part[blockIdx.x] = red[0];
}

__global__ void final2_kernel(float* __restrict__ out)
{
    if (threadIdx.x == 0) {
        double s = 0.0;
        #pragma unroll
        for (int i = 0; i < 8; i++) s += g_part[i];
        out[0] = (float)s;
    }
}

// ============================================================================
extern "C" void kernel_launch(void* const* d_in, const int* in_sizes, int n_in,
                              void* d_out, int out_size)
{
    const float* rij = (const float*)d_in[0];
    const float* Wr1 = (const float*)d_in[1];
    const float* br1 = (const float*)d_in[2];
    const float* Wr2 = (const float*)d_in[3];
    const float* br2 = (const float*)d_in[4];
    const float* Ws1 = (const float*)d_in[5];
    const float* bs1 = (const float*)d_in[6];
    const float* Ws2 = (const float*)d_in[7];
    const float* bs2 = (const float*)d_in[8];
    const float* Wa1 = (const float*)d_in[9];
    const float* ba1 = (const float*)d_in[10];
    const float* Wa2 = (const float*)d_in[11];
    const float* ba2 = (const float*)d_in[12];
    const float* Wa3 = (const float*)d_in[13];
    const float* ba3 = (const float*)d_in[14];
    const int*   fa  = (const int*)d_in[15];
    const int*   sp  = (const int*)d_in[16];
    float* out = (float*)d_out;

    float *ph1, *ph2;
    cudaGetSymbolAddress((void**)&ph1, g_h1);
    cudaGetSymbolAddress((void**)&ph2, g_h2);

    // opt-in to >48KB dynamic smem (idempotent; not an allocation)
    cudaFuncSetAttribute(fused_kernel,
                         cudaFuncAttributeMaxDynamicSharedMemorySize,
                         FUSED_SMEM_BYTES);

    fused_kernel<<<NATOMS, 128, FUSED_SMEM_BYTES>>>(rij, Wr1, br1, Wr2, br2, fa);
    embsort_kernel<<<1, 256>>>(Ws1, bs1, Ws2, bs2, sp);
    weff_kernel<<<dim3(NFEAT, 4), 256>>>(Wa1);
    gemm1_kernel<<<NELEM, 256>>>(ba1);
    gemm2_kernel<<<dim3(H2D / 32, NATOMS / 32), 256>>>(ph1, Wa2, ba2, ph2);
    final1_kernel<<<8, 256>>>(ph2, Wa3, ba3);
    final2_kernel<<<1, 32>>>(out);
}

// round 6
// speedup vs baseline: 2.3575x; 1.2332x over previous
#include <cuda_runtime.h>
#include <math.h>

#define NEDGE 65536
#define NATOMS 2048
#define NK 69
#define NFEAT 216
#define EMBD 16
#define NELEM 94
#define H1D 256
#define H2D 128
#define EC 32        // edges per chunk in fused kernel
#define MAXCHUNK 256 // >= 94 + 2048/16 = 222

// ---------------- scratch (device globals; no allocs allowed) ----------------
__device__ float g_feat[(size_t)NATOMS * NFEAT];      // [nat][216]
__device__ float g_embS[(size_t)NELEM * EMBD];        // [94][16]
__device__ float g_weff[(size_t)NELEM * NFEAT * H1D]; // [94][216][256] 20.8MB
__device__ float g_h1  [(size_t)NATOMS * H1D];
__device__ float g_h2  [(size_t)NATOMS * H2D];
__device__ int   g_alist[NATOMS];
__device__ int   g_ck_lo[MAXCHUNK];
__device__ int   g_ck_hi[MAXCHUNK];
__device__ int   g_ck_s [MAXCHUNK];
__device__ int   g_nchunk;
__device__ double g_part[8];

// ---------------- angular tables (lx,ly,lz, fnorm, lambda) -------------------
// zeta=1: k 0..3, zeta=2: 4..13, zeta=3: 14..33, zeta=4: 34..68
__constant__ int c_lx[NK] = {
 0,0,0,1,
 0,0,0,1,0,0,0,1,1,2,
 0,0,0,1,0,0,0,1,1,2,0,0,0,0,1,1,1,2,2,3,
 0,0,0,1,0,0,0,1,1,2,0,0,0,0,1,1,1,2,2,3,0,0,0,0,0,1,1,1,1,2,2,2,3,3,4};
__constant__ int c_ly[NK] = {
 0,0,1,0,
 0,0,1,0,0,1,2,0,1,0,
 0,0,1,0,0,1,2,0,1,0,0,1,2,3,0,1,2,0,1,0,
 0,0,1,0,0,1,2,0,1,0,0,1,2,3,0,1,2,0,1,0,0,1,2,3,4,0,1,2,3,0,1,2,0,1,0};
__constant__ int c_lz[NK] = {
 0,1,0,0,
 0,1,0,0,2,1,0,1,0,0,
 0,1,0,0,2,1,0,1,0,0,3,2,1,0,2,1,0,1,0,0,
 0,1,0,0,2,1,0,1,0,0,3,2,1,0,2,1,0,1,0,0,4,3,2,1,0,3,2,1,0,2,1,0,1,0,0};
__constant__ float c_fn[NK] = {
 1,1,1,1,
 1,2,2,2,1,2,1,2,2,1,
 1,3,3,3,3,6,3,6,6,3,1,3,3,1,3,6,3,3,3,1,
 1,4,4,4,6,12,6,12,12,6,4,12,12,4,12,24,12,12,12,4,1,4,6,4,1,4,12,12,4,6,12,6,4,4,1};
__constant__ float c_lam[NK] = {
 1,-1,-1,-1,
 1,-1,-1,-1,1,1,1,1,1,1,
 1,-1,-1,-1,1,1,1,1,1,1,-1,-1,-1,-1,-1,-1,-1,-1,-1,-1,
 1,-1,-1,-1,1,1,1,1,1,1,-1,-1,-1,-1,-1,-1,-1,-1,-1,-1,1,1,1,1,1,1,1,1,1,1,1,1,1,1,1};

__device__ __forceinline__ float silu(float x) {
    // x * sigmoid(x) via fast exp + fast reciprocal (err ~1e-6, budget 1e-3)
    return x * __frcp_rn(1.0f + __expf(-x));
}

// ---------------- fused kernel shared-memory layout (float offsets) ----------
#define OFF_W1T 0        // [64][24] transposed Wr1          1536
#define OFF_B1  1536     // [64]                               64
#define OFF_W2  1600     // [64][120] Wr2 natural            7680
#define OFF_B2  9280     // [120]                             120
#define OFF_BAS 9400     // [EC][25]  basis (padded)          800
#define OFF_H   10200    // [EC][65]  hidden (padded)        2080
#define OFF_RAD 12280    // [EC][121] radial out (padded)    3872
#define OFF_GIJ 16152    // [EC][69]  angular combos         2208
#define OFF_GI  18360    // [2][69][24] accumulated gi       3312
#define OFF_F0  21672    // [2][24]   2-body partials          48
#define SMEM_FLOATS 21720
#define FUSED_SMEM_BYTES (SMEM_FLOATS * 4)

// ============================================================================
// Fused kernel: one block (256 threads) per atom. For each chunk of up to 32
// of the atom's edges: P0 geometry (basis + angular combos), P1 radial MLP
// layer1, P2 layer2, P3 per-combo gi accumulation (2 threads per combo, even/
// odd edges). Then assemble the 216 features. No per-edge gmem intermediates.
// ============================================================================
__global__ __launch_bounds__(256) void fused_kernel(
    const float* __restrict__ rij,
    const float* __restrict__ Wr1, const float* __restrict__ br1,
    const float* __restrict__ Wr2, const float* __restrict__ br2,
    const int* __restrict__ fa)
{
    extern __shared__ float sm[];
    int a = blockIdx.x;
    int t = threadIdx.x;

    // cooperative weight staging
    for (int idx = t; idx < 1536; idx += 256) {
        int j = idx / 24, i = idx % 24;
        sm[OFF_W1T + idx] = Wr1[i * 64 + j];      // transpose to [j][i]
    }
    for (int idx = t; idx < 64; idx += 256)   sm[OFF_B1 + idx] = br1[idx];
    for (int idx = t; idx < 7680; idx += 256) sm[OFF_W2 + idx] = Wr2[idx];
    for (int idx = t; idx < 120; idx += 256)  sm[OFF_B2 + idx] = br2[idx];

    // segment bounds via binary search on sorted first_atom_idx
    int lo, hi;
    {
        int l = 0, h = NEDGE;
        while (l < h) { int m = (l + h) >> 1; if (fa[m] < a) l = m + 1; else h = m; }
        lo = l;
        h = NEDGE;
        while (l < h) { int m = (l + h) >> 1; if (fa[m] < a + 1) l = m + 1; else h = m; }
        hi = l;
    }

    int e = t & 31, q = t >> 5;           // P1/P2 roles
    // P3 roles: t<138 -> combo k=t>>1, parity p=t&1; t in [138,186) -> 2-body
    int k3 = t >> 1;
    int p3 = t & 1;
    int c3 = (k3 < 4) ? 1 : (k3 < 14) ? 2 : (k3 < 34) ? 3 : 4;
    float acc[24];
    #pragma unroll
    for (int r = 0; r < 24; r++) acc[r] = 0.f;
    float acc0 = 0.f;
    int r0 = (t - 138) >> 1, p0 = (t - 138) & 1;

    for (int base = lo; base < hi; base += EC) {
        int cnt = min(EC, hi - base);
        __syncthreads();   // protect smem reuse (prev P3 reads / weight staging)

        // ---- P0: per-edge geometry: basis + angular combos (threads 0..cnt-1)
        if (t < cnt) {
            int ed = base + t;
            float x = rij[ed * 3 + 0], y = rij[ed * 3 + 1], z = rij[ed * 3 + 2];
            float r = sqrtf(x * x + y * y + z * z);
            float inv = 1.0f / r;
            float ux = x * inv, uy = y * inv, uz = z * inv;
            float rc = fminf(r, 6.0f);
            float fc = 0.5f * (cosf(3.14159265358979f * rc * (1.0f / 6.0f)) + 1.0f);
            #pragma unroll
            for (int i = 0; i < 24; i++) {
                float d = r - (6.0f * (float)i / 23.0f);
                sm[OFF_BAS + t * 25 + i] = __expf(-8.0f * d * d) * fc;
            }
            float bx = ux + 1e-12f, by = uy + 1e-12f, bz = uz + 1e-12f;
            float px[5], py[5], pz[5];
            px[0] = 1.f; py[0] = 1.f; pz[0] = 1.f;
            #pragma unroll
            for (int l = 1; l < 5; l++) {
                px[l] = px[l - 1] * bx; py[l] = py[l - 1] * by; pz[l] = pz[l - 1] * bz;
            }
            #pragma unroll
            for (int k = 0; k < NK; k++)
                sm[OFF_GIJ + t * 69 + k] = px[c_lx[k]] * py[c_ly[k]] * pz[c_lz[k]] * c_fn[k];
        }
        __syncthreads();

        // ---- P1: layer1 h = silu(basis @ W1 + b1); thread (e, q) does 8 j's
        if (e < cnt) {
            float bas[24];
            #pragma unroll
            for (int i = 0; i < 24; i++) bas[i] = sm[OFF_BAS + e * 25 + i];
            #pragma unroll
            for (int jj = 0; jj < 8; jj++) {
                int j = q * 8 + jj;
                float s = sm[OFF_B1 + j];
                #pragma unroll
                for (int i0 = 0; i0 < 24; i0 += 4) {
                    float4 w = *(const float4*)&sm[OFF_W1T + j * 24 + i0];
                    s = fmaf(bas[i0 + 0], w.x, s);
                    s = fmaf(bas[i0 + 1], w.y, s);
                    s = fmaf(bas[i0 + 2], w.z, s);
                    s = fmaf(bas[i0 + 3], w.w, s);
                }
                sm[OFF_H + e * 65 + j] = silu(s);
            }
        }
        __syncthreads();

        // ---- P2: layer2 rad = silu(h @ W2 + b2); thread (e, q) does 4-wide
        //          output groups i in [q*4, min(q*4+4,30))
        if (e < cnt) {
            float hreg[64];
            #pragma unroll
            for (int j = 0; j < 64; j++) hreg[j] = sm[OFF_H + e * 65 + j];
            int ib = q * 4, iend = min(q * 4 + 4, 30);
            for (int i = ib; i < iend; i++) {
                int o0 = i * 4;
                float a0 = sm[OFF_B2 + o0 + 0];
                float a1 = sm[OFF_B2 + o0 + 1];
                float a2 = sm[OFF_B2 + o0 + 2];
                float a3 = sm[OFF_B2 + o0 + 3];
                #pragma unroll
                for (int j = 0; j < 64; j++) {
                    float4 w = *(const float4*)&sm[OFF_W2 + j * 120 + o0];
                    float hv = hreg[j];
                    a0 = fmaf(hv, w.x, a0);
                    a1 = fmaf(hv, w.y, a1);
                    a2 = fmaf(hv, w.z, a2);
                    a3 = fmaf(hv, w.w, a3);
                }
                sm[OFF_RAD + e * 121 + o0 + 0] = silu(a0);
                sm[OFF_RAD + e * 121 + o0 + 1] = silu(a1);
                sm[OFF_RAD + e * 121 + o0 + 2] = silu(a2);
                sm[OFF_RAD + e * 121 + o0 + 3] = silu(a3);
            }
        }
        __syncthreads();

        // ---- P3: accumulate gi[k][r] (2 threads/combo over edge parity) and
        //          the 2-body term (2 threads/radial channel)
        if (t < 2 * NK) {
            for (int i = p3; i < cnt; i += 2) {
                float g = sm[OFF_GIJ + i * 69 + k3];
                #pragma unroll
                for (int r = 0; r < 24; r++)
                    acc[r] = fmaf(sm[OFF_RAD + i * 121 + r * 5 + c3], g, acc[r]);
            }
        } else if (t < 2 * NK + 48) {
            for (int i = p0; i < cnt; i += 2) acc0 += sm[OFF_RAD + i * 121 + r0 * 5];
        }
    }
    __syncthreads();
    if (t < 2 * NK) {
        #pragma unroll
        for (int r = 0; r < 24; r++) sm[OFF_GI + (p3 * NK + k3) * 24 + r] = acc[r];
    } else if (t < 2 * NK + 48) {
        sm[OFF_F0 + p0 * 24 + r0] = acc0;
    }
    __syncthreads();

    // ---- features: [0:24]=2-body; then per zeta: lam+ (24), lam- (24)
    float* fo = g_feat + (size_t)a * NFEAT;
    for (int f = t; f < NFEAT; f += 256) {
        float v;
        if (f < 24) {
            v = sm[OFF_F0 + f] + sm[OFF_F0 + 24 + f];
        } else {
            int b   = f - 24;
            int blk = b / 24;       // 0..7
            int r   = b % 24;
            int zi  = blk >> 1;     // zeta index 0..3
            int sgn = blk & 1;      // 0: lambda=+1, 1: lambda=-1
            int ks = (zi == 0) ? 0 : (zi == 1) ? 4 : (zi == 2) ? 14 : 34;
            int ke = (zi == 0) ? 4 : (zi == 1) ? 14 : (zi == 2) ? 34 : 69;
            float s = 0.f;
            for (int k = ks; k < ke; k++) {
                float gv = sm[OFF_GI + k * 24 + r] + sm[OFF_GI + (NK + k) * 24 + r];
                float g2 = gv * gv;
                s += sgn ? g2 * c_lam[k] : g2;
            }
            v = s * (1.0f / (float)(1 << zi));   // 2^(1-z), z = zi+1
        }
        fo[f] = v;
    }
}

// ============================================================================
// per-species embedding embS[94][16] + counting sort + chunk list (one block)
// ============================================================================
__global__ __launch_bounds__(256) void embsort_kernel(
    const float* __restrict__ Ws1, const float* __restrict__ bs1,
    const float* __restrict__ Ws2, const float* __restrict__ bs2,
    const int* __restrict__ species)
{
    __shared__ int cnt[NELEM];
    __shared__ int cur[NELEM];
    __shared__ int start[NELEM + 1];
    int t = threadIdx.x;

    if (t < NELEM) {
        int s = t;
        float hv[32];
        #pragma unroll
        for (int j = 0; j < 32; j++) hv[j] = silu(Ws1[s * 32 + j] + bs1[j]);
        #pragma unroll
        for (int m = 0; m < EMBD; m++) {
            float acc = bs2[m];
            #pragma unroll
            for (int j = 0; j < 32; j++) acc = fmaf(hv[j], Ws2[j * EMBD + m], acc);
            g_embS[s * EMBD + m] = acc;
        }
    }

    for (int i = t; i < NELEM; i += 256) cnt[i] = 0;
    __syncthreads();
    for (int a = t; a < NATOMS; a += 256) atomicAdd(&cnt[species[a]], 1);
    __syncthreads();
    if (t == 0) {
        int run = 0;
        for (int s = 0; s < NELEM; s++) {
            start[s] = run;
            cur[s] = run;
            run += cnt[s];
        }
        start[NELEM] = run;
        // build chunk list: per-species chunks of <=16 atoms
        int nc = 0;
        for (int s = 0; s < NELEM; s++) {
            for (int c0 = start[s]; c0 < start[s + 1]; c0 += 16) {
                g_ck_lo[nc] = c0;
                g_ck_hi[nc] = min(c0 + 16, start[s + 1]);
                g_ck_s[nc]  = s;
                nc++;
            }
        }
        g_nchunk = nc;
    }
    __syncthreads();
    for (int a = t; a < NATOMS; a += 256) {
        int s = species[a];
        int pos = atomicAdd(&cur[s], 1);
        g_alist[pos] = a;
    }
}

// ============================================================================
// W_eff[s][f][n] = sum_m embS[s][m] * Wa1[(f*16+m)*256 + n]
// grid = (216, 4): blockIdx.x = f, blockIdx.y selects 24-species slab
// ============================================================================
__global__ __launch_bounds__(256) void weff_kernel(const float* __restrict__ Wa1)
{
    __shared__ float Wsm[EMBD][H1D];    // 16KB
    __shared__ float Esm[24 * EMBD];    // 1.5KB
    int f = blockIdx.x;
    int s0 = blockIdx.y * 24;
    int s1 = min(s0 + 24, NELEM);
    int nsp = s1 - s0;
    int n = threadIdx.x;
    for (int idx = n; idx < EMBD * H1D; idx += 256) {
        int m = idx / H1D, nn = idx % H1D;
        Wsm[m][nn] = Wa1[(size_t)(f * EMBD + m) * H1D + nn];
    }
    for (int idx = n; idx < nsp * EMBD; idx += 256)
        Esm[idx] = g_embS[s0 * EMBD + idx];
    __syncthreads();
    for (int si = 0; si < nsp; si++) {
        float acc = 0.f;
        #pragma unroll
        for (int m = 0; m < EMBD; m++) acc = fmaf(Esm[si * EMBD + m], Wsm[m][n], acc);
        g_weff[((size_t)(s0 + si) * NFEAT + f) * H1D + n] = acc;
    }
}

// ============================================================================
// grouped GEMM: h1[a,n] = silu(sum_f feat[a,f]*W_eff[s,f,n] + ba1[n])
// grid = (MAXCHUNK, 2): blockIdx.x = chunk (<=16 atoms, single species),
// blockIdx.y = 128-wide n-half. 256 threads: nn = y*128 + (t&127), atoms
// split 8+8 by t>>7. One chunk per block, no serial loop.
// ============================================================================
__global__ __launch_bounds__(256) void gemm1_kernel(const float* __restrict__ ba1)
{
    __shared__ float sf[16][NFEAT];   // 13.8KB
    __shared__ int   satom[16];
    int ck = blockIdx.x;
    if (ck >= g_nchunk) return;
    int t = threadIdx.x;
    int lo = g_ck_lo[ck], hi = g_ck_hi[ck], s = g_ck_s[ck];
    int cnt = hi - lo;
    int nn = blockIdx.y * 128 + (t & 127);
    int half = t >> 7;

    if (t < 16) satom[t] = (t < cnt) ? g_alist[lo + t] : -1;
    __syncthreads();
    for (int idx = t; idx < 16 * NFEAT; idx += 256) {
        int m = idx / NFEAT, f = idx % NFEAT;
        int a = satom[m];
        sf[m][f] = (a >= 0) ? g_feat[(size_t)a * NFEAT + f] : 0.f;
    }
    __syncthreads();

    float bias = ba1[nn];
    const float* W = g_weff + (size_t)s * NFEAT * H1D + nn;
    int m0 = half * 8;

    float acc[8];
    #pragma unroll
    for (int m = 0; m < 8; m++) acc[m] = 0.f;
    #pragma unroll 2
    for (int f = 0; f < NFEAT; f += 4) {
        float w0 = W[(size_t)(f + 0) * H1D];
        float w1 = W[(size_t)(f + 1) * H1D];
        float w2 = W[(size_t)(f + 2) * H1D];
        float w3 = W[(size_t)(f + 3) * H1D];
        #pragma unroll
        for (int m = 0; m < 8; m++) {
            float4 fv = *(const float4*)&sf[m0 + m][f];
            acc[m] = fmaf(fv.x, w0, acc[m]);
            acc[m] = fmaf(fv.y, w1, acc[m]);
            acc[m] = fmaf(fv.z, w2, acc[m]);
            acc[m] = fmaf(fv.w, w3, acc[m]);
        }
    }
    #pragma unroll
    for (int m = 0; m < 8; m++) {
        int a = satom[m0 + m];
        if (a >= 0) g_h1[(size_t)a * H1D + nn] = silu(acc[m] + bias);
    }
}

// ============================================================================
// GEMM2, 32x32 tiles: h2 = silu(h1 @ Wa2 + ba2); grid (4, 64), 256 threads
// ============================================================================
__global__ __launch_bounds__(256) void gemm2_kernel(
    const float* __restrict__ A, const float* __restrict__ B,
    const float* __restrict__ bias, float* __restrict__ C)
{
    const int N = H2D, K = H1D;
    __shared__ float As[32][33];
    __shared__ float Bs[32][33];
    int tid = threadIdx.x;
    int bm = blockIdx.y * 32, bn = blockIdx.x * 32;
    int lrow = tid / 8;            // 0..31
    int lcol = (tid % 8) * 4;      // 0,4,...,28
    int ty = tid / 16, tx = tid % 16;

    float acc[2][2] = {};
    for (int k0 = 0; k0 < K; k0 += 32) {
        float4 av = *(const float4*)(A + (size_t)(bm + lrow) * K + k0 + lcol);
        As[lcol + 0][lrow] = av.x;
        As[lcol + 1][lrow] = av.y;
        As[lcol + 2][lrow] = av.z;
        As[lcol + 3][lrow] = av.w;
        float4 bv = *(const float4*)(B + (size_t)(k0 + lrow) * N + bn + lcol);
        Bs[lrow][lcol + 0] = bv.x;
        Bs[lrow][lcol + 1] = bv.y;
        Bs[lrow][lcol + 2] = bv.z;
        Bs[lrow][lcol + 3] = bv.w;
        __syncthreads();
        #pragma unroll
        for (int kk = 0; kk < 32; kk++) {
            float a0 = As[kk][ty * 2 + 0];
            float a1 = As[kk][ty * 2 + 1];
            float b0 = Bs[kk][tx * 2 + 0];
            float b1 = Bs[kk][tx * 2 + 1];
            acc[0][0] = fmaf(a0, b0, acc[0][0]);
            acc[0][1] = fmaf(a0, b1, acc[0][1]);
            acc[1][0] = fmaf(a1, b0, acc[1][0]);
            acc[1][1] = fmaf(a1, b1, acc[1][1]);
        }
        __syncthreads();
    }
    #pragma unroll
    for (int i = 0; i < 2; i++) {
        int m = bm + ty * 2 + i;
        #pragma unroll
        for (int j = 0; j < 2; j++) {
            int nn = bn + tx * 2 + j;
            C[(size_t)m * N + nn] = silu(acc[i][j] + bias[nn]);
        }
    }
}

// ============================================================================
// final reduction: 8 blocks x 256 threads (one atom each) -> g_part; then sum
// ============================================================================
__global__ __launch_bounds__(256) void final1_kernel(
    const float* __restrict__ h2, const float* __restrict__ Wa3,
    const float* __restrict__ ba3)
{
    __shared__ float w[H2D];
    __shared__ double red[256];
    int t = threadIdx.x;
    if (t < H2D) w[t] = Wa3[t];
    __syncthreads();
    int a = blockIdx.x * 256 + t;
    const float* hp = h2 + (size_t)a * H2D;
    float acc = 0.f;
    #pragma unroll 4
    for (int j = 0; j < H2D; j++) acc = fmaf(hp[j], w[j], acc);
    red[t] = (double)(acc + ba3[0]);
    __syncthreads();
    for (int off = 128; off > 0; off >>= 1) {
        if (t < off) red[t] += red[t + off];
        __syncthreads();
    }
    if (t == 0) g_part[blockIdx.x] = red[0];
}

__global__ void final2_kernel(float* __restrict__ out)
{
    if (threadIdx.x == 0) {
        double s = 0.0;
        #pragma unroll
        for (int i = 0; i < 8; i++) s += g_part[i];
        out[0] = (float)s;
    }
}

// ============================================================================
extern "C" void kernel_launch(void* const* d_in, const int* in_sizes, int n_in,
                              void* d_out, int out_size)
{
    const float* rij = (const float*)d_in[0];
    const float* Wr1 = (const float*)d_in[1];
    const float* br1 = (const float*)d_in[2];
    const float* Wr2 = (const float*)d_in[3];
    const float* br2 = (const float*)d_in[4];
    const float* Ws1 = (const float*)d_in[5];
    const float* bs1 = (const float*)d_in[6];
    const float* Ws2 = (const float*)d_in[7];
    const float* bs2 = (const float*)d_in[8];
    const float* Wa1 = (const float*)d_in[9];
    const float* ba1 = (const float*)d_in[10];
    const float* Wa2 = (const float*)d_in[11];
    const float* ba2 = (const float*)d_in[12];
    const float* Wa3 = (const float*)d_in[13];
    const float* ba3 = (const float*)d_in[14];
    const int*   fa  = (const int*)d_in[15];
    const int*   sp  = (const int*)d_in[16];
    float* out = (float*)d_out;

    float *ph1, *ph2;
    cudaGetSymbolAddress((void**)&ph1, g_h1);
    cudaGetSymbolAddress((void**)&ph2, g_h2);

    // opt-in to >48KB dynamic smem (idempotent; not an allocation)
    cudaFuncSetAttribute(fused_kernel,
                         cudaFuncAttributeMaxDynamicSharedMemorySize,
                         FUSED_SMEM_BYTES);

    fused_kernel<<<NATOMS, 256, FUSED_SMEM_BYTES>>>(rij, Wr1, br1, Wr2, br2, fa);
    embsort_kernel<<<1, 256>>>(Ws1, bs1, Ws2, bs2, sp);
    weff_kernel<<<dim3(NFEAT, 4), 256>>>(Wa1);
    gemm1_kernel<<<dim3(MAXCHUNK, 2), 256>>>(ba1);
    gemm2_kernel<<<dim3(H2D / 32, NATOMS / 32), 256>>>(ph1, Wa2, ba2, ph2);
    final1_kernel<<<8, 256>>>(ph2, Wa3, ba3);
    final2_kernel<<<1, 32>>>(out);
}

// round 8
// speedup vs baseline: 2.5572x; 1.0847x over previous
#include <cuda_runtime.h>
#include <math.h>

#define NEDGE 65536
#define NATOMS 2048
#define NK 69
#define NFEAT 216
#define EMBD 16
#define NELEM 94
#define H1D 256
#define H2D 128
#define EC 32        // edges per chunk in fused kernel
#define MAXCHUNK 256

// ---------------- scratch (device globals; no allocs allowed) ----------------
__device__ float g_feat[(size_t)NATOMS * NFEAT];      // [nat][216]
__device__ float g_embS[(size_t)NELEM * EMBD];        // [94][16]
__device__ float g_weff[(size_t)NELEM * NFEAT * H1D]; // [94][216][256] 20.8MB
__device__ float g_h1  [(size_t)NATOMS * H1D];
__device__ float g_h2  [(size_t)NATOMS * H2D];
__device__ int   g_alist[NATOMS];
__device__ int   g_seg[NATOMS + 1];
__device__ int   g_ck_lo[MAXCHUNK];
__device__ int   g_ck_hi[MAXCHUNK];
__device__ int   g_ck_s [MAXCHUNK];
__device__ int   g_nchunk;
__device__ double g_part[8];

// ---------------- angular tables (lx,ly,lz, fnorm, lambda) -------------------
// zeta=1: k 0..3, zeta=2: 4..13, zeta=3: 14..33, zeta=4: 34..68
__constant__ int c_lx[NK] = {
 0,0,0,1,
 0,0,0,1,0,0,0,1,1,2,
 0,0,0,1,0,0,0,1,1,2,0,0,0,0,1,1,1,2,2,3,
 0,0,0,1,0,0,0,1,1,2,0,0,0,0,1,1,1,2,2,3,0,0,0,0,0,1,1,1,1,2,2,2,3,3,4};
__constant__ int c_ly[NK] = {
 0,0,1,0,
 0,0,1,0,0,1,2,0,1,0,
 0,0,1,0,0,1,2,0,1,0,0,1,2,3,0,1,2,0,1,0,
 0,0,1,0,0,1,2,0,1,0,0,1,2,3,0,1,2,0,1,0,0,1,2,3,4,0,1,2,3,0,1,2,0,1,0};
__constant__ int c_lz[NK] = {
 0,1,0,0,
 0,1,0,0,2,1,0,1,0,0,
 0,1,0,0,2,1,0,1,0,0,3,2,1,0,2,1,0,1,0,0,
 0,1,0,0,2,1,0,1,0,0,3,2,1,0,2,1,0,1,0,0,4,3,2,1,0,3,2,1,0,2,1,0,1,0,0};
__constant__ float c_fn[NK] = {
 1,1,1,1,
 1,2,2,2,1,2,1,2,2,1,
 1,3,3,3,3,6,3,6,6,3,1,3,3,1,3,6,3,3,3,1,
 1,4,4,4,6,12,6,12,12,6,4,12,12,4,12,24,12,12,12,4,1,4,6,4,1,4,12,12,4,6,12,6,4,4,1};
__constant__ float c_lam[NK] = {
 1,-1,-1,-1,
 1,-1,-1,-1,1,1,1,1,1,1,
 1,-1,-1,-1,1,1,1,1,1,1,-1,-1,-1,-1,-1,-1,-1,-1,-1,-1,
 1,-1,-1,-1,1,1,1,1,1,1,-1,-1,-1,-1,-1,-1,-1,-1,-1,-1,1,1,1,1,1,1,1,1,1,1,1,1,1,1,1};

__device__ __forceinline__ float silu(float x) {
    // x * sigmoid(x) via fast exp + fast reciprocal (err ~1e-6, budget 1e-3)
    return x * __frcp_rn(1.0f + __expf(-x));
}

// ---------------- fused kernel shared-memory layout (float offsets) ----------
#define OFF_W1T 0        // [64][24] transposed Wr1          1536
#define OFF_B1  1536     // [64]                               64
#define OFF_W2  1600     // [64][120] Wr2 natural            7680
#define OFF_B2  9280     // [120]                             120
#define OFF_BAS 9400     // [EC][25]  basis (padded)          800
#define OFF_H   10200    // [EC][65]  hidden (padded)        2080
#define OFF_RAD 12280    // [EC][121] radial out (padded)    3872
#define OFF_GIJ 16152    // [EC][69]  angular combos         2208
// GI/F0 are only used AFTER the chunk loop -> alias the BAS/H/RAD region
#define OFF_GI  9400     // [2][69][24] accumulated gi       3312 (aliases)
#define OFF_F0  12712    // [2][24]   2-body partials          48 (aliases)
#define SMEM_FLOATS 18360
#define FUSED_SMEM_BYTES (SMEM_FLOATS * 4)   // 73440 B -> 3 blocks/SM

// ============================================================================
// seg_kernel: g_seg[a] = first edge index with fa[e] >= a (fa is sorted)
// ============================================================================
__global__ __launch_bounds__(256) void seg_kernel(const int* __restrict__ fa)
{
    int e = blockIdx.x * 256 + threadIdx.x;
    if (e >= NEDGE) return;
    int cur = fa[e];
    int prev = (e == 0) ? -1 : fa[e - 1];
    for (int a = prev + 1; a <= cur; a++) g_seg[a] = e;
    if (e == NEDGE - 1)
        for (int a = cur + 1; a <= NATOMS; a++) g_seg[a] = NEDGE;
}

// ============================================================================
// Fused kernel: one block (256 threads) per atom. For each chunk of up to 32
// of the atom's edges: P0 geometry (basis + angular combos), P1 radial MLP
// layer1, P2 layer2, P3 per-combo gi accumulation (2 threads per combo, even/
// odd edges). Then assemble the 216 features. No per-edge gmem intermediates.
// ============================================================================
__global__ __launch_bounds__(256) void fused_kernel(
    const float* __restrict__ rij,
    const float* __restrict__ Wr1, const float* __restrict__ br1,
    const float* __restrict__ Wr2, const float* __restrict__ br2)
{
    extern __shared__ float sm[];
    int a = blockIdx.x;
    int t = threadIdx.x;

    // cooperative weight staging
    for (int idx = t; idx < 1536; idx += 256) {
        int j = idx / 24, i = idx % 24;
        sm[OFF_W1T + idx] = Wr1[i * 64 + j];      // transpose to [j][i]
    }
    for (int idx = t; idx < 64; idx += 256)   sm[OFF_B1 + idx] = br1[idx];
    for (int idx = t; idx < 7680; idx += 256) sm[OFF_W2 + idx] = Wr2[idx];
    for (int idx = t; idx < 120; idx += 256)  sm[OFF_B2 + idx] = br2[idx];

    int lo = g_seg[a], hi = g_seg[a + 1];   // precomputed segment bounds

    int e = t & 31, q = t >> 5;           // P1/P2 roles
    // P3 roles: t<138 -> combo k=t>>1, parity p=t&1; t in [138,186) -> 2-body
    int k3 = t >> 1;
    int p3 = t & 1;
    int c3 = (k3 < 4) ? 1 : (k3 < 14) ? 2 : (k3 < 34) ? 3 : 4;
    float acc[24];
    #pragma unroll
    for (int r = 0; r < 24; r++) acc[r] = 0.f;
    float acc0 = 0.f;
    int r0 = (t - 138) >> 1, p0 = (t - 138) & 1;

    for (int base = lo; base < hi; base += EC) {
        int cnt = min(EC, hi - base);
        __syncthreads();   // protect smem reuse (prev P3 reads / weight staging)

        // ---- P0: per-edge geometry: basis + angular combos (threads 0..cnt-1)
        if (t < cnt) {
            int ed = base + t;
            float x = rij[ed * 3 + 0], y = rij[ed * 3 + 1], z = rij[ed * 3 + 2];
            float r = sqrtf(x * x + y * y + z * z);
            float inv = 1.0f / r;
            float ux = x * inv, uy = y * inv, uz = z * inv;
            float rc = fminf(r, 6.0f);
            float fc = 0.5f * (cosf(3.14159265358979f * rc * (1.0f / 6.0f)) + 1.0f);
            #pragma unroll
            for (int i = 0; i < 24; i++) {
                float d = r - (6.0f * (float)i / 23.0f);
                sm[OFF_BAS + t * 25 + i] = __expf(-8.0f * d * d) * fc;
            }
            float bx = ux + 1e-12f, by = uy + 1e-12f, bz = uz + 1e-12f;
            float px[5], py[5], pz[5];
            px[0] = 1.f; py[0] = 1.f; pz[0] = 1.f;
            #pragma unroll
            for (int l = 1; l < 5; l++) {
                px[l] = px[l - 1] * bx; py[l] = py[l - 1] * by; pz[l] = pz[l - 1] * bz;
            }
            #pragma unroll
            for (int k = 0; k < NK; k++)
                sm[OFF_GIJ + t * 69 + k] = px[c_lx[k]] * py[c_ly[k]] * pz[c_lz[k]] * c_fn[k];
        }
        __syncthreads();

        // ---- P1: layer1 h = silu(basis @ W1 + b1); thread (e, q) does 8 j's
        if (e < cnt) {
            float bas[24];
            #pragma unroll
            for (int i = 0; i < 24; i++) bas[i] = sm[OFF_BAS + e * 25 + i];
            #pragma unroll
            for (int jj = 0; jj < 8; jj++) {
                int j = q * 8 + jj;
                float s = sm[OFF_B1 + j];
                #pragma unroll
                for (int i0 = 0; i0 < 24; i0 += 4) {
                    float4 w = *(const float4*)&sm[OFF_W1T + j * 24 + i0];
                    s = fmaf(bas[i0 + 0], w.x, s);
                    s = fmaf(bas[i0 + 1], w.y, s);
                    s = fmaf(bas[i0 + 2], w.z, s);
                    s = fmaf(bas[i0 + 3], w.w, s);
                }
                sm[OFF_H + e * 65 + j] = silu(s);
            }
        }
        __syncthreads();

        // ---- P2: layer2 rad = silu(h @ W2 + b2); thread (e, q) does 4-wide
        //          output groups i in [q*4, min(q*4+4,30))
        if (e < cnt) {
            float hreg[64];
            #pragma unroll
            for (int j = 0; j < 64; j++) hreg[j] = sm[OFF_H + e * 65 + j];
            int ib = q * 4, iend = min(q * 4 + 4, 30);
            for (int i = ib; i < iend; i++) {
                int o0 = i * 4;
                float a0 = sm[OFF_B2 + o0 + 0];
                float a1 = sm[OFF_B2 + o0 + 1];
                float a2 = sm[OFF_B2 + o0 + 2];
                float a3 = sm[OFF_B2 + o0 + 3];
                #pragma unroll
                for (int j = 0; j < 64; j++) {
                    float4 w = *(const float4*)&sm[OFF_W2 + j * 120 + o0];
                    float hv = hreg[j];
                    a0 = fmaf(hv, w.x, a0);
                    a1 = fmaf(hv, w.y, a1);
                    a2 = fmaf(hv, w.z, a2);
                    a3 = fmaf(hv, w.w, a3);
                }
                sm[OFF_RAD + e * 121 + o0 + 0] = silu(a0);
                sm[OFF_RAD + e * 121 + o0 + 1] = silu(a1);
                sm[OFF_RAD + e * 121 + o0 + 2] = silu(a2);
                sm[OFF_RAD + e * 121 + o0 + 3] = silu(a3);
            }
        }
        __syncthreads();

        // ---- P3: accumulate gi[k][r] (2 threads/combo over edge parity) and
        //          the 2-body term (2 threads/radial channel)
        if (t < 2 * NK) {
            for (int i = p3; i < cnt; i += 2) {
                float g = sm[OFF_GIJ + i * 69 + k3];
                #pragma unroll
                for (int r = 0; r < 24; r++)
                    acc[r] = fmaf(sm[OFF_RAD + i * 121 + r * 5 + c3], g, acc[r]);
            }
        } else if (t < 2 * NK + 48) {
            for (int i = p0; i < cnt; i += 2) acc0 += sm[OFF_RAD + i * 121 + r0 * 5];
        }
    }
    __syncthreads();   // after this, BAS/H/RAD region is dead -> GI/F0 alias it
    if (t < 2 * NK) {
        #pragma unroll
        for (int r = 0; r < 24; r++) sm[OFF_GI + (p3 * NK + k3) * 24 + r] = acc[r];
    } else if (t < 2 * NK + 48) {
        sm[OFF_F0 + p0 * 24 + r0] = acc0;
    }
    __syncthreads();

    // ---- features: [0:24]=2-body; then per zeta: lam+ (24), lam- (24)
    float* fo = g_feat + (size_t)a * NFEAT;
    for (int f = t; f < NFEAT; f += 256) {
        float v;
        if (f < 24) {
            v = sm[OFF_F0 + f] + sm[OFF_F0 + 24 + f];
        } else {
            int b   = f - 24;
            int blk = b / 24;       // 0..7
            int r   = b % 24;
            int zi  = blk >> 1;     // zeta index 0..3
            int sgn = blk & 1;      // 0: lambda=+1, 1: lambda=-1
            int ks = (zi == 0) ? 0 : (zi == 1) ? 4 : (zi == 2) ? 14 : 34;
            int ke = (zi == 0) ? 4 : (zi == 1) ? 14 : (zi == 2) ? 34 : 69;
            float s = 0.f;
            for (int k = ks; k < ke; k++) {
                float gv = sm[OFF_GI + k * 24 + r] + sm[OFF_GI + (NK + k) * 24 + r];
                float g2 = gv * gv;
                s += sgn ? g2 * c_lam[k] : g2;
            }
            v = s * (1.0f / (float)(1 << zi));   // 2^(1-z), z = zi+1
        }
        fo[f] = v;
    }
}

// ============================================================================
// per-species embedding embS[94][16] + counting sort + 32-atom chunk list
// ============================================================================
__global__ __launch_bounds__(256) void embsort_kernel(
    const float* __restrict__ Ws1, const float* __restrict__ bs1,
    const float* __restrict__ Ws2, const float* __restrict__ bs2,
    const int* __restrict__ species)
{
    __shared__ int cnt[NELEM];
    __shared__ int cur[NELEM];
    __shared__ int start[NELEM + 1];
    int t = threadIdx.x;

    if (t < NELEM) {
        int s = t;
        float hv[32];
        #pragma unroll
        for (int j = 0; j < 32; j++) hv[j] = silu(Ws1[s * 32 + j] + bs1[j]);
        #pragma unroll
        for (int m = 0; m < EMBD; m++) {
            float acc = bs2[m];
            #pragma unroll
            for (int j = 0; j < 32; j++) acc = fmaf(hv[j], Ws2[j * EMBD + m], acc);
            g_embS[s * EMBD + m] = acc;
        }
    }

    for (int i = t; i < NELEM; i += 256) cnt[i] = 0;
    __syncthreads();
    for (int a = t; a < NATOMS; a += 256) atomicAdd(&cnt[species[a]], 1);
    __syncthreads();
    if (t == 0) {
        int run = 0;
        for (int s = 0; s < NELEM; s++) {
            start[s] = run;
            cur[s] = run;
            run += cnt[s];
        }
        start[NELEM] = run;
        // build chunk list: per-species chunks of <=32 atoms
        int nc = 0;
        for (int s = 0; s < NELEM; s++) {
            for (int c0 = start[s]; c0 < start[s + 1]; c0 += 32) {
                g_ck_lo[nc] = c0;
                g_ck_hi[nc] = min(c0 + 32, start[s + 1]);
                g_ck_s[nc]  = s;
                nc++;
            }
        }
        g_nchunk = nc;
    }
    __syncthreads();
    for (int a = t; a < NATOMS; a += 256) {
        int s = species[a];
        int pos = atomicAdd(&cur[s], 1);
        g_alist[pos] = a;
    }
}

// ============================================================================
// W_eff[s][f][n] = sum_m embS[s][m] * Wa1[(f*16+m)*256 + n]
// grid = (216, 4): blockIdx.x = f, blockIdx.y selects 24-species slab
// ============================================================================
__global__ __launch_bounds__(256) void weff_kernel(const float* __restrict__ Wa1)
{
    __shared__ float Wsm[EMBD][H1D];    // 16KB
    __shared__ float Esm[24 * EMBD];    // 1.5KB
    int f = blockIdx.x;
    int s0 = blockIdx.y * 24;
    int s1 = min(s0 + 24, NELEM);
    int nsp = s1 - s0;
    int n = threadIdx.x;
    for (int idx = n; idx < EMBD * H1D; idx += 256) {
        int m = idx / H1D, nn = idx % H1D;
        Wsm[m][nn] = Wa1[(size_t)(f * EMBD + m) * H1D + nn];
    }
    for (int idx = n; idx < nsp * EMBD; idx += 256)
        Esm[idx] = g_embS[s0 * EMBD + idx];
    __syncthreads();
    for (int si = 0; si < nsp; si++) {
        float acc = 0.f;
        #pragma unroll
        for (int m = 0; m < EMBD; m++) acc = fmaf(Esm[si * EMBD + m], Wsm[m][n], acc);
        g_weff[((size_t)(s0 + si) * NFEAT + f) * H1D + n] = acc;
    }
}

// ============================================================================
// grouped GEMM: h1[a,n] = silu(sum_f feat[a,f]*W_eff[s,f,n] + ba1[n])
// grid = (MAXCHUNK, 2): blockIdx.x = chunk (<=32 atoms, single species),
// blockIdx.y = 128-wide n-half. 256 threads: nn = y*128 + (t&127); the 32
// atoms split 16+16 by t>>7. One chunk per block, 16-deep register blocking.
// ============================================================================
__global__ __launch_bounds__(256) void gemm1_kernel(const float* __restrict__ ba1)
{
    __shared__ float sf[32][NFEAT];   // 27.6KB
    __shared__ int   satom[32];
    int ck = blockIdx.x;
    if (ck >= g_nchunk) return;
    int t = threadIdx.x;
    int lo = g_ck_lo[ck], hi = g_ck_hi[ck], s = g_ck_s[ck];
    int cnt = hi - lo;
    int nn = blockIdx.y * 128 + (t & 127);
    int m0 = (t >> 7) * 16;

    if (t < 32) satom[t] = (t < cnt) ? g_alist[lo + t] : -1;
    __syncthreads();
    for (int idx = t; idx < 32 * NFEAT; idx += 256) {
        int m = idx / NFEAT, f = idx % NFEAT;
        int a = satom[m];
        sf[m][f] = (a >= 0) ? g_feat[(size_t)a * NFEAT + f] : 0.f;
    }
    __syncthreads();

    float bias = ba1[nn];
    const float* W = g_weff + (size_t)s * NFEAT * H1D + nn;

    float acc[16];
    #pragma unroll
    for (int m = 0; m < 16; m++) acc[m] = 0.f;
    for (int f = 0; f < NFEAT; f += 4) {
        float w0 = W[(size_t)(f + 0) * H1D];
        float w1 = W[(size_t)(f + 1) * H1D];
        float w2 = W[(size_t)(f + 2) * H1D];
        float w3 = W[(size_t)(f + 3) * H1D];
        #pragma unroll
        for (int m = 0; m < 16; m++) {
            float4 fv = *(const float4*)&sf[m0 + m][f];
            acc[m] = fmaf(fv.x, w0, acc[m]);
            acc[m] = fmaf(fv.y, w1, acc[m]);
            acc[m] = fmaf(fv.z, w2, acc[m]);
            acc[m] = fmaf(fv.w, w3, acc[m]);
        }
    }
    #pragma unroll
    for (int m = 0; m < 16; m++) {
        int a = satom[m0 + m];
        if (a >= 0) g_h1[(size_t)a * H1D + nn] = silu(acc[m] + bias);
    }
}

// ============================================================================
// GEMM2, 32x32 tiles: h2 = silu(h1 @ Wa2 + ba2); grid (4, 64), 256 threads
// ============================================================================
__global__ __launch_bounds__(256) void gemm2_kernel(
    const float* __restrict__ A, const float* __restrict__ B,
    const float* __restrict__ bias, float* __restrict__ C)
{
    const int N = H2D, K = H1D;
    __shared__ float As[32][33];
    __shared__ float Bs[32][33];
    int tid = threadIdx.x;
    int bm = blockIdx.y * 32, bn = blockIdx.x * 32;
    int lrow = tid / 8;            // 0..31
    int lcol = (tid % 8) * 4;      // 0,4,...,28
    int ty = tid / 16, tx = tid % 16;

    float acc[2][2] = {};
    for (int k0 = 0; k0 < K; k0 += 32) {
        float4 av = *(const float4*)(A + (size_t)(bm + lrow) * K + k0 + lcol);
        As[lcol + 0][lrow] = av.x;
        As[lcol + 1][lrow] = av.y;
        As[lcol + 2][lrow] = av.z;
        As[lcol + 3][lrow] = av.w;
        float4 bv = *(const float4*)(B + (size_t)(k0 + lrow) * N + bn + lcol);
        Bs[lrow][lcol + 0] = bv.x;
        Bs[lrow][lcol + 1] = bv.y;
        Bs[lrow][lcol + 2] = bv.z;
        Bs[lrow][lcol + 3] = bv.w;
        __syncthreads();
        #pragma unroll
        for (int kk = 0; kk < 32; kk++) {
            float a0 = As[kk][ty * 2 + 0];
            float a1 = As[kk][ty * 2 + 1];
            float b0 = Bs[kk][tx * 2 + 0];
            float b1 = Bs[kk][tx * 2 + 1];
            acc[0][0] = fmaf(a0, b0, acc[0][0]);
            acc[0][1] = fmaf(a0, b1, acc[0][1]);
            acc[1][0] = fmaf(a1, b0, acc[1][0]);
            acc[1][1] = fmaf(a1, b1, acc[1][1]);
        }
        __syncthreads();
    }
    #pragma unroll
    for (int i = 0; i < 2; i++) {
        int m = bm + ty * 2 + i;
        #pragma unroll
        for (int j = 0; j < 2; j++) {
            int nn = bn + tx * 2 + j;
            C[(size_t)m * N + nn] = silu(acc[i][j] + bias[nn]);
        }
    }
}

// ============================================================================
// final reduction: 8 blocks x 256 threads (one atom each) -> g_part; then sum
// ============================================================================
__global__ __launch_bounds__(256) void final1_kernel(
    const float* __restrict__ h2, const float* __restrict__ Wa3,
    const float* __restrict__ ba3)
{
    __shared__ float w[H2D];
    __shared__ double red[256];
    int t = threadIdx.x;
    if (t < H2D) w[t] = Wa3[t];
    __syncthreads();
    int a = blockIdx.x * 256 + t;
    const float* hp = h2 + (size_t)a * H2D;
    float acc = 0.f;
    #pragma unroll 4
    for (int j = 0; j < H2D; j++) acc = fmaf(hp[j], w[j], acc);
    red[t] = (double)(acc + ba3[0]);
    __syncthreads();
    for (int off = 128; off > 0; off >>= 1) {
        if (t < off) red[t] += red[t + off];
        __syncthreads();
    }
    if (t == 0) g_part[blockIdx.x] = red[0];
}

__global__ void final2_kernel(float* __restrict__ out)
{
    if (threadIdx.x == 0) {
        double s = 0.0;
        #pragma unroll
        for (int i = 0; i < 8; i++) s += g_part[i];
        out[0] = (float)s;
    }
}

// ============================================================================
extern "C" void kernel_launch(void* const* d_in, const int* in_sizes, int n_in,
                              void* d_out, int out_size)
{
    const float* rij = (const float*)d_in[0];
    const float* Wr1 = (const float*)d_in[1];
    const float* br1 = (const float*)d_in[2];
    const float* Wr2 = (const float*)d_in[3];
    const float* br2 = (const float*)d_in[4];
    const float* Ws1 = (const float*)d_in[5];
    const float* bs1 = (const float*)d_in[6];
    const float* Ws2 = (const float*)d_in[7];
    const float* bs2 = (const float*)d_in[8];
    const float* Wa1 = (const float*)d_in[9];
    const float* ba1 = (const float*)d_in[10];
    const float* Wa2 = (const float*)d_in[11];
    const float* ba2 = (const float*)d_in[12];
    const float* Wa3 = (const float*)d_in[13];
    const float* ba3 = (const float*)d_in[14];
    const int*   fa  = (const int*)d_in[15];
    const int*   sp  = (const int*)d_in[16];
    float* out = (float*)d_out;

    float *ph1, *ph2;
    cudaGetSymbolAddress((void**)&ph1, g_h1);
    cudaGetSymbolAddress((void**)&ph2, g_h2);

    // opt-in to >48KB dynamic smem (idempotent; not an allocation)
    cudaFuncSetAttribute(fused_kernel,
                         cudaFuncAttributeMaxDynamicSharedMemorySize,
                         FUSED_SMEM_BYTES);

    seg_kernel<<<NEDGE / 256, 256>>>(fa);
    fused_kernel<<<NATOMS, 256, FUSED_SMEM_BYTES>>>(rij, Wr1, br1, Wr2, br2);
    embsort_kernel<<<1, 256>>>(Ws1, bs1, Ws2, bs2, sp);
    weff_kernel<<<dim3(NFEAT, 4), 256>>>(Wa1);
    gemm1_kernel<<<dim3(MAXCHUNK, 2), 256>>>(ba1);
    gemm2_kernel<<<dim3(H2D / 32, NATOMS / 32), 256>>>(ph1, Wa2, ba2, ph2);
    final1_kernel<<<8, 256>>>(ph2, Wa3, ba3);
    final2_kernel<<<1, 32>>>(out);
}